// round 13
// baseline (speedup 1.0000x reference)
#include <cuda_runtime.h>
#include <cuda_fp16.h>
#include <mma.h>
#include <cstdint>
#include <cstddef>
#include <math_constants.h>

using namespace nvcuda;

// Problem constants
static constexpr int B  = 4;
static constexpr int S  = 2048;
static constexpr int E  = 1024;
static constexpr int H  = 16;
static constexpr int DK = 64;
static constexpr int BH = B * H;      // 64
static constexpr int M_TOK = B * S;   // 8192

// ---------------- scratch (device globals; no cudaMalloc allowed) ----------------
__device__ __half g_xhi[(size_t)M_TOK * E], g_xlo[(size_t)M_TOK * E];
__device__ __half g_Wqt[(size_t)3 * E * E];
__device__ __half g_Wot[(size_t)E * E];
__device__ __half g_Qhi[(size_t)BH * S * DK], g_Qlo[(size_t)BH * S * DK];
__device__ __half g_K  [(size_t)BH * S * DK];
__device__ __half g_Vt [(size_t)BH * DK * S];
__device__ __half g_vals[(size_t)M_TOK * E];
__device__ float g_rm[(size_t)BH * S], g_ri[(size_t)BH * S];

// ---------------- helpers ----------------
__device__ __forceinline__ uint32_t smem_to_u32(const void* p) {
    uint32_t a;
    asm("{ .reg .u64 t; cvta.to.shared.u64 t, %1; cvt.u32.u64 %0, t; }" : "=r"(a) : "l"(p));
    return a;
}
__device__ __forceinline__ void cp_async16(uint32_t dst, const void* src) {
    asm volatile("cp.async.cg.shared.global [%0], [%1], 16;" :: "r"(dst), "l"(src));
}
#define CP_COMMIT() asm volatile("cp.async.commit_group;" ::: "memory")
#define CP_WAIT(N)  asm volatile("cp.async.wait_group %0;" :: "n"(N) : "memory")

__device__ __forceinline__ uint32_t pack2h(float a, float b) {
    __half2 p(__float2half(a), __float2half(b));
    return *reinterpret_cast<uint32_t*>(&p);
}
__device__ __forceinline__ void split2h(float v, __half& h, __half& l) {
    h = __float2half(v);
    l = __float2half(v - __half2float(h));
}
__device__ __forceinline__ void pack_split2h(float a, float b, uint32_t& hi, uint32_t& lo) {
    __half ha, la, hb, lb;
    split2h(a, ha, la); split2h(b, hb, lb);
    __half2 Hp(ha, hb), Lp(la, lb);
    hi = *reinterpret_cast<uint32_t*>(&Hp);
    lo = *reinterpret_cast<uint32_t*>(&Lp);
}

// ---------------- epilogues for projection GEMMs (BN=128, LDC=136) ----------------
struct EpiQKV {
    const float* bias;
    __device__ void run(int /*z*/, int m0, int n0, int tid, const float* Cs) const {
        #pragma unroll
        for (int it = 0; it < 16; it++) {
            int idx = it * 256 + tid;
            int r = idx >> 5;
            int c4 = (idx & 31) * 4;
            float4 v = *reinterpret_cast<const float4*>(Cs + r * 136 + c4);
            int c = n0 + c4;
            v.x += bias[c]; v.y += bias[c + 1]; v.z += bias[c + 2]; v.w += bias[c + 3];
            int h = c / 192, cc = c - h * 192;
            int t = cc >> 6, d0 = cc & 63;
            int gr = m0 + r;
            int b = gr >> 11, s = gr & 2047;
            int bh = b * H + h;
            if (t == 2) {
                float vv[4] = {v.x, v.y, v.z, v.w};
                #pragma unroll
                for (int i = 0; i < 4; i++)
                    g_Vt[((size_t)bh * DK + d0 + i) * S + s] = __float2half(vv[i]);
            } else if (t == 1) {
                size_t off = ((size_t)bh * S + s) * DK + d0;
                *reinterpret_cast<uint2*>(g_K + off) =
                    make_uint2(pack2h(v.x, v.y), pack2h(v.z, v.w));
            } else {
                uint32_t h0, l0, h1, l1;
                pack_split2h(v.x, v.y, h0, l0);
                pack_split2h(v.z, v.w, h1, l1);
                size_t off = ((size_t)bh * S + s) * DK + d0;
                *reinterpret_cast<uint2*>(g_Qhi + off) = make_uint2(h0, h1);
                *reinterpret_cast<uint2*>(g_Qlo + off) = make_uint2(l0, l1);
            }
        }
    }
};

struct EpiOut {
    const float* bias;
    float* out;
    __device__ void run(int /*z*/, int m0, int n0, int tid, const float* Cs) const {
        #pragma unroll
        for (int it = 0; it < 16; it++) {
            int idx = it * 256 + tid;
            int r = idx >> 5;
            int c4 = (idx & 31) * 4;
            float4 v = *reinterpret_cast<const float4*>(Cs + r * 136 + c4);
            int c = n0 + c4;
            v.x += bias[c]; v.y += bias[c + 1]; v.z += bias[c + 2]; v.w += bias[c + 3];
            *reinterpret_cast<float4*>(out + (size_t)(m0 + r) * E + c) = v;
        }
    }
};

// ---------------- cp.async pipelined fp16 WMMA GEMM (BK=32, 2 CTAs/SM) ------------
template<int BM, int BN, int AP, class Epi>
__global__ void __launch_bounds__(256, 2)
gemm_async(const __half* __restrict__ Ahi, const __half* __restrict__ Alo,
           const __half* __restrict__ Bs, int K, size_t sAz, size_t sBz, Epi epi)
{
    constexpr int LD = 40;
    constexpr int STG_BYTES = (AP * BM + BN) * LD * 2;
    constexpr int WM = 32, WN = BN / 2;
    constexpr int MI = WM / 16, NI = WN / 16;
    constexpr int LDC = BN + 8;

    extern __shared__ char smem[];
    const uint32_t sbase = smem_to_u32(smem);
    const int tid = threadIdx.x, wid = tid >> 5;
    const int z = blockIdx.z;
    const int m0 = blockIdx.y * BM, n0 = blockIdx.x * BN;
    const int wm0 = (wid & 3) * WM, wn0 = (wid >> 2) * WN;

    Ahi += (size_t)z * sAz;
    if (AP == 2) Alo += (size_t)z * sAz;
    Bs += (size_t)z * sBz;

    const int nchunks = K >> 5;

    auto stage = [&](int s, int ch) {
        const int k0 = ch << 5;
        const uint32_t sA = sbase + s * STG_BYTES;
        const uint32_t sB = sA + AP * BM * LD * 2;
        for (int u = tid; u < BM * 4; u += 256) {
            int r = u >> 2, g = u & 3;
            size_t gi = (size_t)(m0 + r) * K + k0 + g * 8;
            uint32_t so = sA + (uint32_t)(r * LD + g * 8) * 2;
            cp_async16(so, Ahi + gi);
            if (AP == 2) cp_async16(so + BM * LD * 2, Alo + gi);
        }
        for (int u = tid; u < BN * 4; u += 256) {
            int r = u >> 2, g = u & 3;
            size_t gi = (size_t)(n0 + r) * K + k0 + g * 8;
            cp_async16(sB + (uint32_t)(r * LD + g * 8) * 2, Bs + gi);
        }
        CP_COMMIT();
    };

    wmma::fragment<wmma::accumulator, 16, 16, 16, float> acc[MI][NI];
    #pragma unroll
    for (int mi = 0; mi < MI; mi++)
        #pragma unroll
        for (int ni = 0; ni < NI; ni++) wmma::fill_fragment(acc[mi][ni], 0.0f);

    stage(0, 0);
    for (int ch = 0; ch < nchunks; ch++) {
        if (ch + 1 < nchunks) { stage((ch + 1) & 1, ch + 1); CP_WAIT(1); }
        else                  { CP_WAIT(0); }
        __syncthreads();

        const __half* As_hi =
            reinterpret_cast<const __half*>(smem + (ch & 1) * STG_BYTES);
        const __half* As_lo = As_hi + BM * LD;
        const __half* Bs_s  = As_hi + AP * BM * LD;

        #pragma unroll
        for (int ks = 0; ks < 2; ks++) {
            wmma::fragment<wmma::matrix_a, 16, 16, 16, __half, wmma::row_major> ah[MI], al[MI];
            wmma::fragment<wmma::matrix_b, 16, 16, 16, __half, wmma::col_major> bf[NI];
            #pragma unroll
            for (int mi = 0; mi < MI; mi++) {
                wmma::load_matrix_sync(ah[mi], As_hi + (wm0 + mi * 16) * LD + ks * 16, LD);
                if (AP == 2)
                    wmma::load_matrix_sync(al[mi], As_lo + (wm0 + mi * 16) * LD + ks * 16, LD);
            }
            #pragma unroll
            for (int ni = 0; ni < NI; ni++)
                wmma::load_matrix_sync(bf[ni], Bs_s + (wn0 + ni * 16) * LD + ks * 16, LD);
            #pragma unroll
            for (int mi = 0; mi < MI; mi++)
                #pragma unroll
                for (int ni = 0; ni < NI; ni++) {
                    wmma::mma_sync(acc[mi][ni], ah[mi], bf[ni], acc[mi][ni]);
                    if (AP == 2)
                        wmma::mma_sync(acc[mi][ni], al[mi], bf[ni], acc[mi][ni]);
                }
        }
        __syncthreads();
    }

    float* Cs = reinterpret_cast<float*>(smem);
    #pragma unroll
    for (int mi = 0; mi < MI; mi++)
        #pragma unroll
        for (int ni = 0; ni < NI; ni++)
            wmma::store_matrix_sync(Cs + (wm0 + mi * 16) * LDC + wn0 + ni * 16,
                                    acc[mi][ni], LDC, wmma::mem_row_major);
    __syncthreads();
    epi.run(z, m0, n0, tid, Cs);
}

// ---------------- STATS kernel: 128-wide chunks, 32x64 warp tiles ------------------
__global__ void __launch_bounds__(256, 1)
stats_kernel(const __half* __restrict__ Qhi, const __half* __restrict__ Qlo,
             const __half* __restrict__ Kp,
             float* __restrict__ rm, float* __restrict__ ri)
{
    constexpr int LDQ = 72, LDK = 72, LDC = 136;
    constexpr int K_STG = 128 * LDK * 2;  // 18432
    constexpr int OFF_Q = 0;              // 36864
    constexpr int OFF_K = 36864;          // 2 x 18432
    constexpr int OFF_C = 73728;          // 128*136*4 = 69632
    constexpr int OFF_M = 143360;         // 512
    constexpr int OFF_S = 143872;         // 512 ; total 144384

    extern __shared__ char smem[];
    const uint32_t sbase = smem_to_u32(smem);
    const int tid = threadIdx.x, wid = tid >> 5, lane = tid & 31;
    const int z = blockIdx.z, m0 = blockIdx.y * 128;
    const int wm0 = (wid & 3) * 32, wn0 = (wid >> 2) * 64;

    const __half* Qh_g = Qhi + ((size_t)z * S + m0) * DK;
    const __half* Ql_g = Qlo + ((size_t)z * S + m0) * DK;
    const __half* K_g  = Kp  + (size_t)z * S * DK;

    for (int u = tid; u < 128 * 8; u += 256) {
        int r = u >> 3, g = u & 7;
        cp_async16(sbase + OFF_Q + (uint32_t)(r * LDQ + g * 8) * 2, Qh_g + (size_t)r * DK + g * 8);
        cp_async16(sbase + OFF_Q + 18432 + (uint32_t)(r * LDQ + g * 8) * 2, Ql_g + (size_t)r * DK + g * 8);
    }
    CP_COMMIT();
    auto stage_k = [&](int s, int ch) {
        int k0 = ch << 7;
        for (int u = tid; u < 128 * 8; u += 256) {
            int r = u >> 3, g = u & 7;
            cp_async16(sbase + OFF_K + s * K_STG + (uint32_t)(r * LDK + g * 8) * 2,
                       K_g + (size_t)(k0 + r) * DK + g * 8);
        }
        CP_COMMIT();
    };
    stage_k(0, 0);

    float* sM = reinterpret_cast<float*>(smem + OFF_M);
    float* sS = reinterpret_cast<float*>(smem + OFF_S);
    if (tid < 128) { sM[tid] = -CUDART_INF_F; sS[tid] = 0.0f; }

    const __half* sQh = reinterpret_cast<const __half*>(smem + OFF_Q);
    const __half* sQl = reinterpret_cast<const __half*>(smem + OFF_Q + 18432);
    float* Cs = reinterpret_cast<float*>(smem + OFF_C);

    for (int ch = 0; ch < 16; ch++) {
        if (ch + 1 < 16) { stage_k((ch + 1) & 1, ch + 1); CP_WAIT(1); }
        else             { CP_WAIT(0); }
        __syncthreads();
        const __half* sK = reinterpret_cast<const __half*>(smem + OFF_K + (ch & 1) * K_STG);

        wmma::fragment<wmma::accumulator, 16, 16, 16, float> acc[2][4];
        #pragma unroll
        for (int mi = 0; mi < 2; mi++)
            #pragma unroll
            for (int ni = 0; ni < 4; ni++) wmma::fill_fragment(acc[mi][ni], 0.0f);

        #pragma unroll
        for (int ks = 0; ks < 4; ks++) {
            wmma::fragment<wmma::matrix_a, 16, 16, 16, __half, wmma::row_major> ah[2], al[2];
            wmma::fragment<wmma::matrix_b, 16, 16, 16, __half, wmma::col_major> bf[4];
            #pragma unroll
            for (int mi = 0; mi < 2; mi++) {
                wmma::load_matrix_sync(ah[mi], sQh + (wm0 + mi * 16) * LDQ + ks * 16, LDQ);
                wmma::load_matrix_sync(al[mi], sQl + (wm0 + mi * 16) * LDQ + ks * 16, LDQ);
            }
            #pragma unroll
            for (int ni = 0; ni < 4; ni++)
                wmma::load_matrix_sync(bf[ni], sK + (wn0 + ni * 16) * LDK + ks * 16, LDK);
            #pragma unroll
            for (int mi = 0; mi < 2; mi++)
                #pragma unroll
                for (int ni = 0; ni < 4; ni++) {
                    wmma::mma_sync(acc[mi][ni], ah[mi], bf[ni], acc[mi][ni]);
                    wmma::mma_sync(acc[mi][ni], al[mi], bf[ni], acc[mi][ni]);
                }
        }
        #pragma unroll
        for (int mi = 0; mi < 2; mi++)
            #pragma unroll
            for (int ni = 0; ni < 4; ni++)
                wmma::store_matrix_sync(Cs + (wm0 + mi * 16) * LDC + wn0 + ni * 16,
                                        acc[mi][ni], LDC, wmma::mem_row_major);
        __syncthreads();

        // per-row reduce: one warp covers one 128-col row
        #pragma unroll
        for (int it = 0; it < 16; it++) {
            int idx = it * 256 + tid;
            int r = idx >> 5, c4 = lane * 4;
            float4 v = *reinterpret_cast<const float4*>(Cs + r * LDC + c4);
            v.x *= 0.125f; v.y *= 0.125f; v.z *= 0.125f; v.w *= 0.125f;
            float tm = fmaxf(fmaxf(v.x, v.y), fmaxf(v.z, v.w));
            #pragma unroll
            for (int o = 16; o > 0; o >>= 1) tm = fmaxf(tm, __shfl_xor_sync(0xFFFFFFFFu, tm, o));
            float ts = __expf(v.x - tm) + __expf(v.y - tm) + __expf(v.z - tm) + __expf(v.w - tm);
            #pragma unroll
            for (int o = 16; o > 0; o >>= 1) ts += __shfl_xor_sync(0xFFFFFFFFu, ts, o);
            if (lane == 0) {
                float om = sM[r], os = sS[r];
                float nm = fmaxf(om, tm);
                sS[r] = os * __expf(om - nm) + ts * __expf(tm - nm);
                sM[r] = nm;
            }
        }
        __syncthreads();
    }

    if (tid < 128) {
        size_t ro = (size_t)z * S + m0 + tid;
        rm[ro] = sM[tid];
        ri[ro] = 1.0f / sS[tid];
    }
}

// ---------------- PV2: 128-wide chunks, warp-local transform ----------------------
__global__ void __launch_bounds__(256, 1)
pv2_kernel(float* __restrict__ attn,
           const float* __restrict__ rm, const float* __restrict__ ri,
           const __half* __restrict__ Qhi, const __half* __restrict__ Qlo,
           const __half* __restrict__ Kp, const __half* __restrict__ Vt)
{
    constexpr int LDQ = 72, LDK = 72, LDV = 136, LDCF = 136, LDP = 136;
    constexpr int K_STG = 128 * LDK * 2;   // 18432
    constexpr int V_STG = 64 * LDV * 2;    // 17408
    constexpr int OFF_Q  = 0;              // 36864
    constexpr int OFF_K  = 36864;          // 2 x 18432 = 36864
    constexpr int OFF_V  = 73728;          // 2 x 17408 = 34816
    constexpr int OFF_C  = 108544;         // 128*136*4 = 69632
    constexpr int OFF_P  = 178176;         // 128*136*2 = 34816
    constexpr int OFF_RM = 212992;         // 512
    constexpr int OFF_RI = 213504;         // 512 ; total 214016

    extern __shared__ char smem[];
    const uint32_t sbase = smem_to_u32(smem);
    const int tid = threadIdx.x, wid = tid >> 5, lane = tid & 31;
    const int z = blockIdx.z, m0 = blockIdx.y * 128;
    const int wm0 = (wid & 3) * 32, wn0 = (wid >> 2) * 64;   // QK tile
    const int wnP = (wid >> 2) * 32;                          // PV tile

    const __half* Qh_g = Qhi + ((size_t)z * S + m0) * DK;
    const __half* Ql_g = Qlo + ((size_t)z * S + m0) * DK;
    const __half* K_g  = Kp  + (size_t)z * S * DK;
    const __half* V_g  = Vt  + (size_t)z * DK * S;
    float* attnZ = attn + (size_t)z * S * S;

    for (int u = tid; u < 128 * 8; u += 256) {
        int r = u >> 3, g = u & 7;
        cp_async16(sbase + OFF_Q + (uint32_t)(r * LDQ + g * 8) * 2, Qh_g + (size_t)r * DK + g * 8);
        cp_async16(sbase + OFF_Q + 18432 + (uint32_t)(r * LDQ + g * 8) * 2, Ql_g + (size_t)r * DK + g * 8);
    }
    CP_COMMIT();
    auto stage_kv = [&](int s, int ch) {
        int k0 = ch << 7;
        for (int u = tid; u < 128 * 8; u += 256) {
            int r = u >> 3, g = u & 7;
            cp_async16(sbase + OFF_K + s * K_STG + (uint32_t)(r * LDK + g * 8) * 2,
                       K_g + (size_t)(k0 + r) * DK + g * 8);
        }
        for (int u = tid; u < 64 * 16; u += 256) {
            int r = u >> 4, g = u & 15;
            cp_async16(sbase + OFF_V + s * V_STG + (uint32_t)(r * LDV + g * 8) * 2,
                       V_g + (size_t)r * S + k0 + g * 8);
        }
        CP_COMMIT();
    };
    stage_kv(0, 0);

    float* sRm = reinterpret_cast<float*>(smem + OFF_RM);
    float* sRi = reinterpret_cast<float*>(smem + OFF_RI);
    if (tid < 128) {
        size_t ro = (size_t)z * S + m0 + tid;
        sRm[tid] = rm[ro];
        sRi[tid] = ri[ro];
    }

    const __half* sQh = reinterpret_cast<const __half*>(smem + OFF_Q);
    const __half* sQl = reinterpret_cast<const __half*>(smem + OFF_Q + 18432);
    float* Csf = reinterpret_cast<float*>(smem + OFF_C);
    __half* Ph = reinterpret_cast<__half*>(smem + OFF_P);

    wmma::fragment<wmma::accumulator, 16, 16, 16, float> pacc[2][2];
    #pragma unroll
    for (int mi = 0; mi < 2; mi++)
        #pragma unroll
        for (int ni = 0; ni < 2; ni++) wmma::fill_fragment(pacc[mi][ni], 0.0f);

    for (int ch = 0; ch < 16; ch++) {
        __syncthreads();   // prev PV MMA complete: KV bufs + Ph reusable; sRm/sRi visible

        if (ch + 1 < 16) { stage_kv((ch + 1) & 1, ch + 1); CP_WAIT(1); }
        else             { CP_WAIT(0); }
        __syncthreads();   // KV[ch] visible

        const __half* sK = reinterpret_cast<const __half*>(smem + OFF_K + (ch & 1) * K_STG);
        const __half* sV = reinterpret_cast<const __half*>(smem + OFF_V + (ch & 1) * V_STG);

        // ---- QK^T recompute (identical arithmetic to stats_kernel) ----
        wmma::fragment<wmma::accumulator, 16, 16, 16, float> qacc[2][4];
        #pragma unroll
        for (int mi = 0; mi < 2; mi++)
            #pragma unroll
            for (int ni = 0; ni < 4; ni++) wmma::fill_fragment(qacc[mi][ni], 0.0f);
        #pragma unroll
        for (int ks = 0; ks < 4; ks++) {
            wmma::fragment<wmma::matrix_a, 16, 16, 16, __half, wmma::row_major> ah[2], al[2];
            wmma::fragment<wmma::matrix_b, 16, 16, 16, __half, wmma::col_major> bf[4];
            #pragma unroll
            for (int mi = 0; mi < 2; mi++) {
                wmma::load_matrix_sync(ah[mi], sQh + (wm0 + mi * 16) * LDQ + ks * 16, LDQ);
                wmma::load_matrix_sync(al[mi], sQl + (wm0 + mi * 16) * LDQ + ks * 16, LDQ);
            }
            #pragma unroll
            for (int ni = 0; ni < 4; ni++)
                wmma::load_matrix_sync(bf[ni], sK + (wn0 + ni * 16) * LDK + ks * 16, LDK);
            #pragma unroll
            for (int mi = 0; mi < 2; mi++)
                #pragma unroll
                for (int ni = 0; ni < 4; ni++) {
                    wmma::mma_sync(qacc[mi][ni], ah[mi], bf[ni], qacc[mi][ni]);
                    wmma::mma_sync(qacc[mi][ni], al[mi], bf[ni], qacc[mi][ni]);
                }
        }
        #pragma unroll
        for (int mi = 0; mi < 2; mi++)
            #pragma unroll
            for (int ni = 0; ni < 4; ni++)
                wmma::store_matrix_sync(Csf + (wm0 + mi * 16) * LDCF + wn0 + ni * 16,
                                        qacc[mi][ni], LDCF, wmma::mem_row_major);
        __syncwarp();   // warp-local: own tile stores visible to own lanes

        // ---- transform (warp-local 32x64 tile): probs -> attn + Ph ----
        const int n0 = ch << 7;
        #pragma unroll
        for (int j = 0; j < 16; j++) {
            int t = j * 32 + lane;
            int row = wm0 + (t >> 4);
            int col = wn0 + (t & 15) * 4;
            float4 v = *reinterpret_cast<const float4*>(Csf + row * LDCF + col);
            float m = sRm[row], rv = sRi[row];
            float4 p;
            p.x = __expf(v.x * 0.125f - m) * rv;
            p.y = __expf(v.y * 0.125f - m) * rv;
            p.z = __expf(v.z * 0.125f - m) * rv;
            p.w = __expf(v.w * 0.125f - m) * rv;
            *reinterpret_cast<float4*>(attnZ + (size_t)(m0 + row) * S + n0 + col) = p;
            *reinterpret_cast<uint2*>(Ph + row * LDP + col) =
                make_uint2(pack2h(p.x, p.y), pack2h(p.z, p.w));
        }
        __syncthreads();   // Ph complete across warps

        // ---- PV MMA: K-dim = 128, single pass fp16 probs ----
        #pragma unroll
        for (int ks = 0; ks < 8; ks++) {
            wmma::fragment<wmma::matrix_a, 16, 16, 16, __half, wmma::row_major> af[2];
            wmma::fragment<wmma::matrix_b, 16, 16, 16, __half, wmma::col_major> bf[2];
            #pragma unroll
            for (int mi = 0; mi < 2; mi++)
                wmma::load_matrix_sync(af[mi], Ph + (wm0 + mi * 16) * LDP + ks * 16, LDP);
            #pragma unroll
            for (int ni = 0; ni < 2; ni++)
                wmma::load_matrix_sync(bf[ni], sV + (wnP + ni * 16) * LDV + ks * 16, LDV);
            #pragma unroll
            for (int mi = 0; mi < 2; mi++)
                #pragma unroll
                for (int ni = 0; ni < 2; ni++)
                    wmma::mma_sync(pacc[mi][ni], af[mi], bf[ni], pacc[mi][ni]);
        }
    }
    __syncthreads();

    // ---- epilogue: values -> g_vals single fp16 [B,S,E] ----
    #pragma unroll
    for (int mi = 0; mi < 2; mi++)
        #pragma unroll
        for (int ni = 0; ni < 2; ni++)
            wmma::store_matrix_sync(Csf + (wm0 + mi * 16) * 72 + wnP + ni * 16,
                                    pacc[mi][ni], 72, wmma::mem_row_major);
    __syncthreads();

    int b = z >> 4, h = z & 15;
    #pragma unroll
    for (int it = 0; it < 8; it++) {
        int idx = it * 256 + tid;
        int r = idx >> 4;
        int c4 = (idx & 15) * 4;
        float4 v = *reinterpret_cast<const float4*>(Csf + r * 72 + c4);
        size_t off = (size_t)(b * S + m0 + r) * E + h * DK + c4;
        *reinterpret_cast<uint2*>(g_vals + off) =
            make_uint2(pack2h(v.x, v.y), pack2h(v.z, v.w));
    }
}

// ---------------- pre-kernels ----------------
__global__ void __launch_bounds__(256)
split_kernel(const float* __restrict__ src, __half* __restrict__ dh,
             __half* __restrict__ dl, size_t n)
{
    size_t i = ((size_t)blockIdx.x * 256 + threadIdx.x) * 4;
    if (i >= n) return;
    float4 v = *reinterpret_cast<const float4*>(src + i);
    uint32_t h0, l0, h1, l1;
    pack_split2h(v.x, v.y, h0, l0);
    pack_split2h(v.z, v.w, h1, l1);
    *reinterpret_cast<uint2*>(dh + i) = make_uint2(h0, h1);
    *reinterpret_cast<uint2*>(dl + i) = make_uint2(l0, l1);
}

__global__ void __launch_bounds__(256)
transpose_h(const float* __restrict__ W, __half* __restrict__ Th, int R, int C)
{
    __shared__ float t[32][33];
    int c0 = blockIdx.x * 32, r0 = blockIdx.y * 32;
    int tx = threadIdx.x & 31, ty = threadIdx.x >> 5;
    for (int j = ty; j < 32; j += 8)
        t[j][tx] = W[(size_t)(r0 + j) * C + c0 + tx];
    __syncthreads();
    for (int j = ty; j < 32; j += 8)
        Th[(size_t)(c0 + j) * R + r0 + tx] = __float2half(t[tx][j]);
}

// ---------------- launch ----------------
extern "C" void kernel_launch(void* const* d_in, const int* /*in_sizes*/, int /*n_in*/,
                              void* d_out, int /*out_size*/)
{
    const float* x    = (const float*)d_in[0];
    const float* Wqkv = (const float*)d_in[1];
    const float* bqkv = (const float*)d_in[2];
    const float* Wout = (const float*)d_in[3];
    const float* bout = (const float*)d_in[4];

    float* out  = (float*)d_out;
    float* attn = out + (size_t)M_TOK * E;

    __half *xhi, *xlo, *Wq, *Wo, *Qhi, *Qlo, *Kp, *Vt, *Vl;
    float *rm, *ri;
    cudaGetSymbolAddress((void**)&xhi, g_xhi);
    cudaGetSymbolAddress((void**)&xlo, g_xlo);
    cudaGetSymbolAddress((void**)&Wq,  g_Wqt);
    cudaGetSymbolAddress((void**)&Wo,  g_Wot);
    cudaGetSymbolAddress((void**)&Qhi, g_Qhi);
    cudaGetSymbolAddress((void**)&Qlo, g_Qlo);
    cudaGetSymbolAddress((void**)&Kp,  g_K);
    cudaGetSymbolAddress((void**)&Vt,  g_Vt);
    cudaGetSymbolAddress((void**)&Vl,  g_vals);
    cudaGetSymbolAddress((void**)&rm,  g_rm);
    cudaGetSymbolAddress((void**)&ri,  g_ri);

    constexpr int SM_BIG   = 69632;
    constexpr int SM_STATS = 144384;
    constexpr int SM_PV2   = 214016;
    cudaFuncSetAttribute(gemm_async<128, 128, 2, EpiQKV>,
                         cudaFuncAttributeMaxDynamicSharedMemorySize, SM_BIG);
    cudaFuncSetAttribute(gemm_async<128, 128, 1, EpiOut>,
                         cudaFuncAttributeMaxDynamicSharedMemorySize, SM_BIG);
    cudaFuncSetAttribute(stats_kernel,
                         cudaFuncAttributeMaxDynamicSharedMemorySize, SM_STATS);
    cudaFuncSetAttribute(pv2_kernel,
                         cudaFuncAttributeMaxDynamicSharedMemorySize, SM_PV2);

    // 0) operand prep
    transpose_h<<<dim3(3 * E / 32, E / 32), 256>>>(Wqkv, Wq, E, 3 * E);
    transpose_h<<<dim3(E / 32, E / 32), 256>>>(Wout, Wo, E, E);
    split_kernel<<<(unsigned)((size_t)M_TOK * E / 4 / 256), 256>>>(x, xhi, xlo, (size_t)M_TOK * E);

    // 1) QKV projection (A = x split, 2-pass)
    gemm_async<128, 128, 2, EpiQKV><<<dim3(3 * E / 128, M_TOK / 128, 1), 256, SM_BIG>>>(
        xhi, xlo, Wq, E, 0, 0, EpiQKV{bqkv});

    // 2) stats: exact per-row (max, 1/sum)
    stats_kernel<<<dim3(1, S / 128, BH), 256, SM_STATS>>>(Qhi, Qlo, Kp, rm, ri);

    // 3) PV2: recompute logits, probs -> attn (single pass), PV
    pv2_kernel<<<dim3(1, S / 128, BH), 256, SM_PV2>>>(attn, rm, ri, Qhi, Qlo, Kp, Vt);

    // 4) output projection (A = vals single fp16, 1-pass)
    gemm_async<128, 128, 1, EpiOut><<<dim3(E / 128, M_TOK / 128, 1), 256, SM_BIG>>>(
        Vl, nullptr, Wo, E, 0, 0, EpiOut{bout, out});
}

// round 14
// speedup vs baseline: 1.3537x; 1.3537x over previous
#include <cuda_runtime.h>
#include <cuda_fp16.h>
#include <mma.h>
#include <cstdint>
#include <cstddef>
#include <math_constants.h>

using namespace nvcuda;

// Problem constants
static constexpr int B  = 4;
static constexpr int S  = 2048;
static constexpr int E  = 1024;
static constexpr int H  = 16;
static constexpr int DK = 64;
static constexpr int BH = B * H;      // 64
static constexpr int M_TOK = B * S;   // 8192

// ---------------- scratch (device globals; no cudaMalloc allowed) ----------------
__device__ __half g_xhi[(size_t)M_TOK * E], g_xlo[(size_t)M_TOK * E];
__device__ __half g_Wqt[(size_t)3 * E * E];
__device__ __half g_Wot[(size_t)E * E];
__device__ __half g_Qhi[(size_t)BH * S * DK], g_Qlo[(size_t)BH * S * DK];
__device__ __half g_K  [(size_t)BH * S * DK];
__device__ __half g_Vt [(size_t)BH * DK * S];
__device__ __half g_vals[(size_t)M_TOK * E];
__device__ float g_rm[(size_t)BH * S], g_ri[(size_t)BH * S];

// ---------------- helpers ----------------
__device__ __forceinline__ uint32_t smem_to_u32(const void* p) {
    uint32_t a;
    asm("{ .reg .u64 t; cvta.to.shared.u64 t, %1; cvt.u32.u64 %0, t; }" : "=r"(a) : "l"(p));
    return a;
}
__device__ __forceinline__ void cp_async16(uint32_t dst, const void* src) {
    asm volatile("cp.async.cg.shared.global [%0], [%1], 16;" :: "r"(dst), "l"(src));
}
#define CP_COMMIT() asm volatile("cp.async.commit_group;" ::: "memory")
#define CP_WAIT(N)  asm volatile("cp.async.wait_group %0;" :: "n"(N) : "memory")

__device__ __forceinline__ uint32_t pack2h(float a, float b) {
    __half2 p(__float2half(a), __float2half(b));
    return *reinterpret_cast<uint32_t*>(&p);
}
__device__ __forceinline__ void split2h(float v, __half& h, __half& l) {
    h = __float2half(v);
    l = __float2half(v - __half2float(h));
}
__device__ __forceinline__ void pack_split2h(float a, float b, uint32_t& hi, uint32_t& lo) {
    __half ha, la, hb, lb;
    split2h(a, ha, la); split2h(b, hb, lb);
    __half2 Hp(ha, hb), Lp(la, lb);
    hi = *reinterpret_cast<uint32_t*>(&Hp);
    lo = *reinterpret_cast<uint32_t*>(&Lp);
}

// ---------------- epilogues for projection GEMMs (BN=128, LDC=136) ----------------
struct EpiQKV {
    const float* bias;
    __device__ void run(int /*z*/, int m0, int n0, int tid, const float* Cs) const {
        // ---- Q / K columns (generic path; V columns skipped) ----
        #pragma unroll
        for (int it = 0; it < 16; it++) {
            int idx = it * 256 + tid;
            int r = idx >> 5;
            int c4 = (idx & 31) * 4;
            int c = n0 + c4;
            int h = c / 192, cc = c - h * 192;
            int t = cc >> 6, d0 = cc & 63;
            if (t == 2) continue;   // V handled by transposed path below
            float4 v = *reinterpret_cast<const float4*>(Cs + r * 136 + c4);
            v.x += bias[c]; v.y += bias[c + 1]; v.z += bias[c + 2]; v.w += bias[c + 3];
            int gr = m0 + r;
            int b = gr >> 11, s = gr & 2047;
            int bh = b * H + h;
            if (t == 1) {
                size_t off = ((size_t)bh * S + s) * DK + d0;
                *reinterpret_cast<uint2*>(g_K + off) =
                    make_uint2(pack2h(v.x, v.y), pack2h(v.z, v.w));
            } else {
                uint32_t h0, l0, h1, l1;
                pack_split2h(v.x, v.y, h0, l0);
                pack_split2h(v.z, v.w, h1, l1);
                size_t off = ((size_t)bh * S + s) * DK + d0;
                *reinterpret_cast<uint2*>(g_Qhi + off) = make_uint2(h0, h1);
                *reinterpret_cast<uint2*>(g_Qlo + off) = make_uint2(l0, l1);
            }
        }
        // ---- V columns: transposed, coalesced along s ----
        const int wid = tid >> 5, lane = tid & 31;
        const int b = m0 >> 11, s0 = m0 & 2047;
        #pragma unroll
        for (int half = 0; half < 2; half++) {
            int cbase = n0 + half * 64;
            int h = cbase / 192, cc = cbase - h * 192;
            if ((cc >> 6) != 2) continue;
            int bh = b * H + h;
            #pragma unroll
            for (int dd = 0; dd < 8; dd++) {
                int d = wid * 8 + dd;
                float bval = bias[cbase + d];
                __half* dst = g_Vt + ((size_t)bh * DK + d) * S + s0;
                #pragma unroll
                for (int sb = 0; sb < 4; sb++) {
                    int r = sb * 32 + lane;
                    float v = Cs[r * 136 + half * 64 + d] + bval;
                    dst[r] = __float2half(v);   // lanes -> consecutive s: coalesced
                }
            }
        }
    }
};

struct EpiOut {
    const float* bias;
    float* out;
    __device__ void run(int /*z*/, int m0, int n0, int tid, const float* Cs) const {
        #pragma unroll
        for (int it = 0; it < 16; it++) {
            int idx = it * 256 + tid;
            int r = idx >> 5;
            int c4 = (idx & 31) * 4;
            float4 v = *reinterpret_cast<const float4*>(Cs + r * 136 + c4);
            int c = n0 + c4;
            v.x += bias[c]; v.y += bias[c + 1]; v.z += bias[c + 2]; v.w += bias[c + 3];
            *reinterpret_cast<float4*>(out + (size_t)(m0 + r) * E + c) = v;
        }
    }
};

// ---------------- cp.async pipelined fp16 WMMA GEMM (BK=32, 2 CTAs/SM) ------------
// AP=2: A split hi/lo (2 MMA passes). AP=1: A single fp16 (1 pass).
template<int BM, int BN, int AP, class Epi>
__global__ void __launch_bounds__(256, 2)
gemm_async(const __half* __restrict__ Ahi, const __half* __restrict__ Alo,
           const __half* __restrict__ Bs, int K, size_t sAz, size_t sBz, Epi epi)
{
    constexpr int LD = 40;
    constexpr int STG_BYTES = (AP * BM + BN) * LD * 2;
    constexpr int WM = 32, WN = BN / 2;
    constexpr int MI = WM / 16, NI = WN / 16;
    constexpr int LDC = BN + 8;

    extern __shared__ char smem[];
    const uint32_t sbase = smem_to_u32(smem);
    const int tid = threadIdx.x, wid = tid >> 5;
    const int z = blockIdx.z;
    const int m0 = blockIdx.y * BM, n0 = blockIdx.x * BN;
    const int wm0 = (wid & 3) * WM, wn0 = (wid >> 2) * WN;

    Ahi += (size_t)z * sAz;
    if (AP == 2) Alo += (size_t)z * sAz;
    Bs += (size_t)z * sBz;

    const int nchunks = K >> 5;

    auto stage = [&](int s, int ch) {
        const int k0 = ch << 5;
        const uint32_t sA = sbase + s * STG_BYTES;
        const uint32_t sB = sA + AP * BM * LD * 2;
        for (int u = tid; u < BM * 4; u += 256) {
            int r = u >> 2, g = u & 3;
            size_t gi = (size_t)(m0 + r) * K + k0 + g * 8;
            uint32_t so = sA + (uint32_t)(r * LD + g * 8) * 2;
            cp_async16(so, Ahi + gi);
            if (AP == 2) cp_async16(so + BM * LD * 2, Alo + gi);
        }
        for (int u = tid; u < BN * 4; u += 256) {
            int r = u >> 2, g = u & 3;
            size_t gi = (size_t)(n0 + r) * K + k0 + g * 8;
            cp_async16(sB + (uint32_t)(r * LD + g * 8) * 2, Bs + gi);
        }
        CP_COMMIT();
    };

    wmma::fragment<wmma::accumulator, 16, 16, 16, float> acc[MI][NI];
    #pragma unroll
    for (int mi = 0; mi < MI; mi++)
        #pragma unroll
        for (int ni = 0; ni < NI; ni++) wmma::fill_fragment(acc[mi][ni], 0.0f);

    stage(0, 0);
    for (int ch = 0; ch < nchunks; ch++) {
        if (ch + 1 < nchunks) { stage((ch + 1) & 1, ch + 1); CP_WAIT(1); }
        else                  { CP_WAIT(0); }
        __syncthreads();

        const __half* As_hi =
            reinterpret_cast<const __half*>(smem + (ch & 1) * STG_BYTES);
        const __half* As_lo = As_hi + BM * LD;
        const __half* Bs_s  = As_hi + AP * BM * LD;

        #pragma unroll
        for (int ks = 0; ks < 2; ks++) {
            wmma::fragment<wmma::matrix_a, 16, 16, 16, __half, wmma::row_major> ah[MI], al[MI];
            wmma::fragment<wmma::matrix_b, 16, 16, 16, __half, wmma::col_major> bf[NI];
            #pragma unroll
            for (int mi = 0; mi < MI; mi++) {
                wmma::load_matrix_sync(ah[mi], As_hi + (wm0 + mi * 16) * LD + ks * 16, LD);
                if (AP == 2)
                    wmma::load_matrix_sync(al[mi], As_lo + (wm0 + mi * 16) * LD + ks * 16, LD);
            }
            #pragma unroll
            for (int ni = 0; ni < NI; ni++)
                wmma::load_matrix_sync(bf[ni], Bs_s + (wn0 + ni * 16) * LD + ks * 16, LD);
            #pragma unroll
            for (int mi = 0; mi < MI; mi++)
                #pragma unroll
                for (int ni = 0; ni < NI; ni++) {
                    wmma::mma_sync(acc[mi][ni], ah[mi], bf[ni], acc[mi][ni]);
                    if (AP == 2)
                        wmma::mma_sync(acc[mi][ni], al[mi], bf[ni], acc[mi][ni]);
                }
        }
        __syncthreads();
    }

    float* Cs = reinterpret_cast<float*>(smem);
    #pragma unroll
    for (int mi = 0; mi < MI; mi++)
        #pragma unroll
        for (int ni = 0; ni < NI; ni++)
            wmma::store_matrix_sync(Cs + (wm0 + mi * 16) * LDC + wn0 + ni * 16,
                                    acc[mi][ni], LDC, wmma::mem_row_major);
    __syncthreads();
    epi.run(z, m0, n0, tid, Cs);
}

// ---------------- STATS kernel: exact row (max, 1/sum) without writing logits ------
__global__ void __launch_bounds__(256, 2)
stats_kernel(const __half* __restrict__ Qhi, const __half* __restrict__ Qlo,
             const __half* __restrict__ Kp,
             float* __restrict__ rm, float* __restrict__ ri)
{
    constexpr int LDQ = 72, LDK = 72, LDC = 72;
    constexpr int OFF_Q = 0;       // Qh 18432 + Ql 18432
    constexpr int OFF_K = 36864;   // 2 x 9216
    constexpr int OFF_C = 55296;   // 36864
    constexpr int OFF_M = 92160;   // 512
    constexpr int OFF_S = 92672;   // 512 ; total 93184

    extern __shared__ char smem[];
    const uint32_t sbase = smem_to_u32(smem);
    const int tid = threadIdx.x, wid = tid >> 5;
    const int z = blockIdx.z, m0 = blockIdx.y * 128;
    const int wm0 = (wid & 3) * 32, wn0 = (wid >> 2) * 32;

    const __half* Qh_g = Qhi + ((size_t)z * S + m0) * DK;
    const __half* Ql_g = Qlo + ((size_t)z * S + m0) * DK;
    const __half* K_g  = Kp  + (size_t)z * S * DK;

    for (int u = tid; u < 128 * 8; u += 256) {
        int r = u >> 3, g = u & 7;
        cp_async16(sbase + OFF_Q + (uint32_t)(r * LDQ + g * 8) * 2, Qh_g + (size_t)r * DK + g * 8);
        cp_async16(sbase + OFF_Q + 18432 + (uint32_t)(r * LDQ + g * 8) * 2, Ql_g + (size_t)r * DK + g * 8);
    }
    CP_COMMIT();
    auto stage_k = [&](int s, int ch) {
        int k0 = ch << 6;
        for (int u = tid; u < 64 * 8; u += 256) {
            int r = u >> 3, g = u & 7;
            cp_async16(sbase + OFF_K + s * 9216 + (uint32_t)(r * LDK + g * 8) * 2,
                       K_g + (size_t)(k0 + r) * DK + g * 8);
        }
        CP_COMMIT();
    };
    stage_k(0, 0);

    float* sM = reinterpret_cast<float*>(smem + OFF_M);
    float* sS = reinterpret_cast<float*>(smem + OFF_S);
    if (tid < 128) { sM[tid] = -CUDART_INF_F; sS[tid] = 0.0f; }

    const __half* sQh = reinterpret_cast<const __half*>(smem + OFF_Q);
    const __half* sQl = reinterpret_cast<const __half*>(smem + OFF_Q + 18432);
    float* Cs = reinterpret_cast<float*>(smem + OFF_C);

    for (int ch = 0; ch < 32; ch++) {
        if (ch + 1 < 32) { stage_k((ch + 1) & 1, ch + 1); CP_WAIT(1); }
        else             { CP_WAIT(0); }
        __syncthreads();
        const __half* sK = reinterpret_cast<const __half*>(smem + OFF_K + (ch & 1) * 9216);

        wmma::fragment<wmma::accumulator, 16, 16, 16, float> acc[2][2];
        #pragma unroll
        for (int mi = 0; mi < 2; mi++)
            #pragma unroll
            for (int ni = 0; ni < 2; ni++) wmma::fill_fragment(acc[mi][ni], 0.0f);

        #pragma unroll
        for (int ks = 0; ks < 4; ks++) {
            wmma::fragment<wmma::matrix_a, 16, 16, 16, __half, wmma::row_major> ah[2], al[2];
            wmma::fragment<wmma::matrix_b, 16, 16, 16, __half, wmma::col_major> bf[2];
            #pragma unroll
            for (int mi = 0; mi < 2; mi++) {
                wmma::load_matrix_sync(ah[mi], sQh + (wm0 + mi * 16) * LDQ + ks * 16, LDQ);
                wmma::load_matrix_sync(al[mi], sQl + (wm0 + mi * 16) * LDQ + ks * 16, LDQ);
            }
            #pragma unroll
            for (int ni = 0; ni < 2; ni++)
                wmma::load_matrix_sync(bf[ni], sK + (wn0 + ni * 16) * LDK + ks * 16, LDK);
            #pragma unroll
            for (int mi = 0; mi < 2; mi++)
                #pragma unroll
                for (int ni = 0; ni < 2; ni++) {
                    wmma::mma_sync(acc[mi][ni], ah[mi], bf[ni], acc[mi][ni]);
                    wmma::mma_sync(acc[mi][ni], al[mi], bf[ni], acc[mi][ni]);
                }
        }
        #pragma unroll
        for (int mi = 0; mi < 2; mi++)
            #pragma unroll
            for (int ni = 0; ni < 2; ni++)
                wmma::store_matrix_sync(Cs + (wm0 + mi * 16) * LDC + wn0 + ni * 16,
                                        acc[mi][ni], LDC, wmma::mem_row_major);
        __syncthreads();

        #pragma unroll
        for (int it = 0; it < 8; it++) {
            int idx = it * 256 + tid;
            int r = idx >> 4, c4 = (idx & 15) * 4;
            float4 v = *reinterpret_cast<const float4*>(Cs + r * LDC + c4);
            v.x *= 0.125f; v.y *= 0.125f; v.z *= 0.125f; v.w *= 0.125f;
            float tm = fmaxf(fmaxf(v.x, v.y), fmaxf(v.z, v.w));
            #pragma unroll
            for (int o = 8; o > 0; o >>= 1) tm = fmaxf(tm, __shfl_xor_sync(0xFFFFFFFFu, tm, o));
            float ts = __expf(v.x - tm) + __expf(v.y - tm) + __expf(v.z - tm) + __expf(v.w - tm);
            #pragma unroll
            for (int o = 8; o > 0; o >>= 1) ts += __shfl_xor_sync(0xFFFFFFFFu, ts, o);
            if ((tid & 15) == 0) {
                float om = sM[r], os = sS[r];
                float nm = fmaxf(om, tm);
                sS[r] = os * __expf(om - nm) + ts * __expf(tm - nm);
                sM[r] = nm;
            }
        }
        __syncthreads();
    }

    if (tid < 128) {
        size_t ro = (size_t)z * S + m0 + tid;
        rm[ro] = sM[tid];
        ri[ro] = 1.0f / sS[tid];
    }
}

// ---------------- PV2: recompute QK^T, softmax -> probs (only attn write), PV ------
__global__ void __launch_bounds__(256, 2)
pv2_kernel(float* __restrict__ attn,
           const float* __restrict__ rm, const float* __restrict__ ri,
           const __half* __restrict__ Qhi, const __half* __restrict__ Qlo,
           const __half* __restrict__ Kp, const __half* __restrict__ Vt)
{
    constexpr int LDQ = 72, LDK = 72, LDV = 72, LDCF = 72, LDP = 72;
    constexpr int OFF_Q  = 0;       // 36864
    constexpr int OFF_K  = 36864;   // 2 x 9216
    constexpr int OFF_V  = 55296;   // 2 x 9216
    constexpr int OFF_C  = 73728;   // 36864 (fp32 logits / fp16 probs overlay)
    constexpr int OFF_RM = 110592;  // 512
    constexpr int OFF_RI = 111104;  // 512 ; total 111616

    extern __shared__ char smem[];
    const uint32_t sbase = smem_to_u32(smem);
    const int tid = threadIdx.x, wid = tid >> 5;
    const int z = blockIdx.z, m0 = blockIdx.y * 128;
    const int wm0 = (wid & 3) * 32, wn0 = (wid >> 2) * 32;

    const __half* Qh_g = Qhi + ((size_t)z * S + m0) * DK;
    const __half* Ql_g = Qlo + ((size_t)z * S + m0) * DK;
    const __half* K_g  = Kp  + (size_t)z * S * DK;
    const __half* V_g  = Vt  + (size_t)z * DK * S;
    float* attnZ = attn + (size_t)z * S * S;

    for (int u = tid; u < 128 * 8; u += 256) {
        int r = u >> 3, g = u & 7;
        cp_async16(sbase + OFF_Q + (uint32_t)(r * LDQ + g * 8) * 2, Qh_g + (size_t)r * DK + g * 8);
        cp_async16(sbase + OFF_Q + 18432 + (uint32_t)(r * LDQ + g * 8) * 2, Ql_g + (size_t)r * DK + g * 8);
    }
    CP_COMMIT();
    auto stage_kv = [&](int s, int ch) {
        int k0 = ch << 6;
        for (int u = tid; u < 64 * 8; u += 256) {
            int r = u >> 3, g = u & 7;
            cp_async16(sbase + OFF_K + s * 9216 + (uint32_t)(r * LDK + g * 8) * 2,
                       K_g + (size_t)(k0 + r) * DK + g * 8);
            cp_async16(sbase + OFF_V + s * 9216 + (uint32_t)(r * LDV + g * 8) * 2,
                       V_g + (size_t)r * S + k0 + g * 8);
        }
        CP_COMMIT();
    };
    stage_kv(0, 0);

    float* sRm = reinterpret_cast<float*>(smem + OFF_RM);
    float* sRi = reinterpret_cast<float*>(smem + OFF_RI);
    if (tid < 128) {
        size_t ro = (size_t)z * S + m0 + tid;
        sRm[tid] = rm[ro];
        sRi[tid] = ri[ro];
    }

    const __half* sQh = reinterpret_cast<const __half*>(smem + OFF_Q);
    const __half* sQl = reinterpret_cast<const __half*>(smem + OFF_Q + 18432);
    float* Csf = reinterpret_cast<float*>(smem + OFF_C);
    __half* Ph = reinterpret_cast<__half*>(smem + OFF_C);

    wmma::fragment<wmma::accumulator, 16, 16, 16, float> pacc[2][2];
    #pragma unroll
    for (int mi = 0; mi < 2; mi++)
        #pragma unroll
        for (int ni = 0; ni < 2; ni++) wmma::fill_fragment(pacc[mi][ni], 0.0f);

    for (int ch = 0; ch < 32; ch++) {
        __syncthreads();   // prev PV MMA complete: KV buf (ch+1)&1 and Ph reusable

        if (ch + 1 < 32) { stage_kv((ch + 1) & 1, ch + 1); CP_WAIT(1); }
        else             { CP_WAIT(0); }
        __syncthreads();   // KV[ch] visible to all threads

        const __half* sK = reinterpret_cast<const __half*>(smem + OFF_K + (ch & 1) * 9216);
        const __half* sV = reinterpret_cast<const __half*>(smem + OFF_V + (ch & 1) * 9216);

        // ---- QK^T recompute (identical arithmetic to stats_kernel) ----
        wmma::fragment<wmma::accumulator, 16, 16, 16, float> qacc[2][2];
        #pragma unroll
        for (int mi = 0; mi < 2; mi++)
            #pragma unroll
            for (int ni = 0; ni < 2; ni++) wmma::fill_fragment(qacc[mi][ni], 0.0f);
        #pragma unroll
        for (int ks = 0; ks < 4; ks++) {
            wmma::fragment<wmma::matrix_a, 16, 16, 16, __half, wmma::row_major> ah[2], al[2];
            wmma::fragment<wmma::matrix_b, 16, 16, 16, __half, wmma::col_major> bf[2];
            #pragma unroll
            for (int mi = 0; mi < 2; mi++) {
                wmma::load_matrix_sync(ah[mi], sQh + (wm0 + mi * 16) * LDQ + ks * 16, LDQ);
                wmma::load_matrix_sync(al[mi], sQl + (wm0 + mi * 16) * LDQ + ks * 16, LDQ);
            }
            #pragma unroll
            for (int ni = 0; ni < 2; ni++)
                wmma::load_matrix_sync(bf[ni], sK + (wn0 + ni * 16) * LDK + ks * 16, LDK);
            #pragma unroll
            for (int mi = 0; mi < 2; mi++)
                #pragma unroll
                for (int ni = 0; ni < 2; ni++) {
                    wmma::mma_sync(qacc[mi][ni], ah[mi], bf[ni], qacc[mi][ni]);
                    wmma::mma_sync(qacc[mi][ni], al[mi], bf[ni], qacc[mi][ni]);
                }
        }
        #pragma unroll
        for (int mi = 0; mi < 2; mi++)
            #pragma unroll
            for (int ni = 0; ni < 2; ni++)
                wmma::store_matrix_sync(Csf + (wm0 + mi * 16) * LDCF + wn0 + ni * 16,
                                        qacc[mi][ni], LDCF, wmma::mem_row_major);
        __syncthreads();

        // ---- transform: exp-normalize, write probs to attn, in-place fp16 pack ----
        const int n0 = ch << 6;
        #pragma unroll
        for (int it = 0; it < 8; it++) {
            int idx = it * 256 + tid;
            int r = idx >> 4, c4 = (idx & 15) * 4;
            float4 v = *reinterpret_cast<const float4*>(Csf + r * LDCF + c4);
            float m = sRm[r], rv = sRi[r];
            float4 p;
            p.x = __expf(v.x * 0.125f - m) * rv;
            p.y = __expf(v.y * 0.125f - m) * rv;
            p.z = __expf(v.z * 0.125f - m) * rv;
            p.w = __expf(v.w * 0.125f - m) * rv;
            *reinterpret_cast<float4*>(attnZ + (size_t)(m0 + r) * S + n0 + c4) = p;
            __syncwarp();   // all Csf reads of this warp's rows complete before overlay
            *reinterpret_cast<uint2*>(Ph + r * LDP + c4) =
                make_uint2(pack2h(p.x, p.y), pack2h(p.z, p.w));
        }
        __syncthreads();

        // ---- PV MMA, single pass on fp16 probs ----
        #pragma unroll
        for (int ks = 0; ks < 4; ks++) {
            wmma::fragment<wmma::matrix_a, 16, 16, 16, __half, wmma::row_major> af[2];
            wmma::fragment<wmma::matrix_b, 16, 16, 16, __half, wmma::col_major> bf[2];
            #pragma unroll
            for (int mi = 0; mi < 2; mi++)
                wmma::load_matrix_sync(af[mi], Ph + (wm0 + mi * 16) * LDP + ks * 16, LDP);
            #pragma unroll
            for (int ni = 0; ni < 2; ni++)
                wmma::load_matrix_sync(bf[ni], sV + (wn0 + ni * 16) * LDV + ks * 16, LDV);
            #pragma unroll
            for (int mi = 0; mi < 2; mi++)
                #pragma unroll
                for (int ni = 0; ni < 2; ni++)
                    wmma::mma_sync(pacc[mi][ni], af[mi], bf[ni], pacc[mi][ni]);
        }
    }
    __syncthreads();

    // ---- epilogue: values -> g_vals single fp16 [B,S,E] ----
    #pragma unroll
    for (int mi = 0; mi < 2; mi++)
        #pragma unroll
        for (int ni = 0; ni < 2; ni++)
            wmma::store_matrix_sync(Csf + (wm0 + mi * 16) * 72 + wn0 + ni * 16,
                                    pacc[mi][ni], 72, wmma::mem_row_major);
    __syncthreads();

    int b = z >> 4, h = z & 15;
    #pragma unroll
    for (int it = 0; it < 8; it++) {
        int idx = it * 256 + tid;
        int r = idx >> 4;
        int c4 = (idx & 15) * 4;
        float4 v = *reinterpret_cast<const float4*>(Csf + r * 72 + c4);
        size_t off = (size_t)(b * S + m0 + r) * E + h * DK + c4;
        *reinterpret_cast<uint2*>(g_vals + off) =
            make_uint2(pack2h(v.x, v.y), pack2h(v.z, v.w));
    }
}

// ---------------- pre-kernels ----------------
__global__ void __launch_bounds__(256)
split_kernel(const float* __restrict__ src, __half* __restrict__ dh,
             __half* __restrict__ dl, size_t n)
{
    size_t i = ((size_t)blockIdx.x * 256 + threadIdx.x) * 4;
    if (i >= n) return;
    float4 v = *reinterpret_cast<const float4*>(src + i);
    uint32_t h0, l0, h1, l1;
    pack_split2h(v.x, v.y, h0, l0);
    pack_split2h(v.z, v.w, h1, l1);
    *reinterpret_cast<uint2*>(dh + i) = make_uint2(h0, h1);
    *reinterpret_cast<uint2*>(dl + i) = make_uint2(l0, l1);
}

__global__ void __launch_bounds__(256)
transpose_h(const float* __restrict__ W, __half* __restrict__ Th, int R, int C)
{
    __shared__ float t[32][33];
    int c0 = blockIdx.x * 32, r0 = blockIdx.y * 32;
    int tx = threadIdx.x & 31, ty = threadIdx.x >> 5;
    for (int j = ty; j < 32; j += 8)
        t[j][tx] = W[(size_t)(r0 + j) * C + c0 + tx];
    __syncthreads();
    for (int j = ty; j < 32; j += 8)
        Th[(size_t)(c0 + j) * R + r0 + tx] = __float2half(t[tx][j]);
}

// ---------------- launch ----------------
extern "C" void kernel_launch(void* const* d_in, const int* /*in_sizes*/, int /*n_in*/,
                              void* d_out, int /*out_size*/)
{
    const float* x    = (const float*)d_in[0];
    const float* Wqkv = (const float*)d_in[1];
    const float* bqkv = (const float*)d_in[2];
    const float* Wout = (const float*)d_in[3];
    const float* bout = (const float*)d_in[4];

    float* out  = (float*)d_out;
    float* attn = out + (size_t)M_TOK * E;

    __half *xhi, *xlo, *Wq, *Wo, *Qhi, *Qlo, *Kp, *Vt, *Vl;
    float *rm, *ri;
    cudaGetSymbolAddress((void**)&xhi, g_xhi);
    cudaGetSymbolAddress((void**)&xlo, g_xlo);
    cudaGetSymbolAddress((void**)&Wq,  g_Wqt);
    cudaGetSymbolAddress((void**)&Wo,  g_Wot);
    cudaGetSymbolAddress((void**)&Qhi, g_Qhi);
    cudaGetSymbolAddress((void**)&Qlo, g_Qlo);
    cudaGetSymbolAddress((void**)&Kp,  g_K);
    cudaGetSymbolAddress((void**)&Vt,  g_Vt);
    cudaGetSymbolAddress((void**)&Vl,  g_vals);
    cudaGetSymbolAddress((void**)&rm,  g_rm);
    cudaGetSymbolAddress((void**)&ri,  g_ri);

    constexpr int SM_BIG   = 69632;
    constexpr int SM_STATS = 93184;
    constexpr int SM_PV2   = 111616;
    cudaFuncSetAttribute(gemm_async<128, 128, 2, EpiQKV>,
                         cudaFuncAttributeMaxDynamicSharedMemorySize, SM_BIG);
    cudaFuncSetAttribute(gemm_async<128, 128, 1, EpiOut>,
                         cudaFuncAttributeMaxDynamicSharedMemorySize, SM_BIG);
    cudaFuncSetAttribute(stats_kernel,
                         cudaFuncAttributeMaxDynamicSharedMemorySize, SM_STATS);
    cudaFuncSetAttribute(pv2_kernel,
                         cudaFuncAttributeMaxDynamicSharedMemorySize, SM_PV2);

    // 0) operand prep
    transpose_h<<<dim3(3 * E / 32, E / 32), 256>>>(Wqkv, Wq, E, 3 * E);
    transpose_h<<<dim3(E / 32, E / 32), 256>>>(Wout, Wo, E, E);
    split_kernel<<<(unsigned)((size_t)M_TOK * E / 4 / 256), 256>>>(x, xhi, xlo, (size_t)M_TOK * E);

    // 1) QKV projection (A = x split, 2-pass)
    gemm_async<128, 128, 2, EpiQKV><<<dim3(3 * E / 128, M_TOK / 128, 1), 256, SM_BIG>>>(
        xhi, xlo, Wq, E, 0, 0, EpiQKV{bqkv});

    // 2) stats: exact per-row (max, 1/sum)
    stats_kernel<<<dim3(1, S / 128, BH), 256, SM_STATS>>>(Qhi, Qlo, Kp, rm, ri);

    // 3) PV2: recompute logits, probs -> attn (single pass), PV (probs single fp16)
    pv2_kernel<<<dim3(1, S / 128, BH), 256, SM_PV2>>>(attn, rm, ri, Qhi, Qlo, Kp, Vt);

    // 4) output projection (A = vals single fp16, 1-pass)
    gemm_async<128, 128, 1, EpiOut><<<dim3(E / 128, M_TOK / 128, 1), 256, SM_BIG>>>(
        Vl, nullptr, Wo, E, 0, 0, EpiOut{bout, out});
}

// round 15
// speedup vs baseline: 1.5048x; 1.1116x over previous
#include <cuda_runtime.h>
#include <cuda_fp16.h>
#include <mma.h>
#include <cstdint>
#include <cstddef>
#include <math_constants.h>

using namespace nvcuda;

// Problem constants
static constexpr int B  = 4;
static constexpr int S  = 2048;
static constexpr int E  = 1024;
static constexpr int H  = 16;
static constexpr int DK = 64;
static constexpr int BH = B * H;      // 64
static constexpr int M_TOK = B * S;   // 8192

// ---------------- scratch (device globals; no cudaMalloc allowed) ----------------
__device__ __half g_xhi[(size_t)M_TOK * E], g_xlo[(size_t)M_TOK * E];
__device__ __half g_Wqt[(size_t)3 * E * E];
__device__ __half g_Wot[(size_t)E * E];
__device__ __half g_Qhi[(size_t)BH * S * DK], g_Qlo[(size_t)BH * S * DK];
__device__ __half g_K  [(size_t)BH * S * DK];
__device__ __half g_Vt [(size_t)BH * DK * S];
__device__ __half g_vals[(size_t)M_TOK * E];
__device__ float g_ri[(size_t)BH * S];

// ---------------- helpers ----------------
__device__ __forceinline__ uint32_t smem_to_u32(const void* p) {
    uint32_t a;
    asm("{ .reg .u64 t; cvta.to.shared.u64 t, %1; cvt.u32.u64 %0, t; }" : "=r"(a) : "l"(p));
    return a;
}
__device__ __forceinline__ void cp_async16(uint32_t dst, const void* src) {
    asm volatile("cp.async.cg.shared.global [%0], [%1], 16;" :: "r"(dst), "l"(src));
}
#define CP_COMMIT() asm volatile("cp.async.commit_group;" ::: "memory")
#define CP_WAIT(N)  asm volatile("cp.async.wait_group %0;" :: "n"(N) : "memory")

__device__ __forceinline__ uint32_t pack2h(float a, float b) {
    __half2 p(__float2half(a), __float2half(b));
    return *reinterpret_cast<uint32_t*>(&p);
}
__device__ __forceinline__ void split2h(float v, __half& h, __half& l) {
    h = __float2half(v);
    l = __float2half(v - __half2float(h));
}
__device__ __forceinline__ void pack_split2h(float a, float b, uint32_t& hi, uint32_t& lo) {
    __half ha, la, hb, lb;
    split2h(a, ha, la); split2h(b, hb, lb);
    __half2 Hp(ha, hb), Lp(la, lb);
    hi = *reinterpret_cast<uint32_t*>(&Hp);
    lo = *reinterpret_cast<uint32_t*>(&Lp);
}

// ---------------- epilogues for projection GEMMs (BN=128, LDC=136) ----------------
struct EpiQKV {
    const float* bias;
    __device__ void run(int /*z*/, int m0, int n0, int tid, const float* Cs) const {
        // ---- Q / K columns (generic path; V columns skipped) ----
        #pragma unroll
        for (int it = 0; it < 16; it++) {
            int idx = it * 256 + tid;
            int r = idx >> 5;
            int c4 = (idx & 31) * 4;
            int c = n0 + c4;
            int h = c / 192, cc = c - h * 192;
            int t = cc >> 6, d0 = cc & 63;
            if (t == 2) continue;   // V handled by transposed path below
            float4 v = *reinterpret_cast<const float4*>(Cs + r * 136 + c4);
            v.x += bias[c]; v.y += bias[c + 1]; v.z += bias[c + 2]; v.w += bias[c + 3];
            int gr = m0 + r;
            int b = gr >> 11, s = gr & 2047;
            int bh = b * H + h;
            if (t == 1) {
                size_t off = ((size_t)bh * S + s) * DK + d0;
                *reinterpret_cast<uint2*>(g_K + off) =
                    make_uint2(pack2h(v.x, v.y), pack2h(v.z, v.w));
            } else {
                uint32_t h0, l0, h1, l1;
                pack_split2h(v.x, v.y, h0, l0);
                pack_split2h(v.z, v.w, h1, l1);
                size_t off = ((size_t)bh * S + s) * DK + d0;
                *reinterpret_cast<uint2*>(g_Qhi + off) = make_uint2(h0, h1);
                *reinterpret_cast<uint2*>(g_Qlo + off) = make_uint2(l0, l1);
            }
        }
        // ---- V columns: transposed, coalesced along s ----
        const int wid = tid >> 5, lane = tid & 31;
        const int b = m0 >> 11, s0 = m0 & 2047;
        #pragma unroll
        for (int half = 0; half < 2; half++) {
            int cbase = n0 + half * 64;
            int h = cbase / 192, cc = cbase - h * 192;
            if ((cc >> 6) != 2) continue;
            int bh = b * H + h;
            #pragma unroll
            for (int dd = 0; dd < 8; dd++) {
                int d = wid * 8 + dd;
                float bval = bias[cbase + d];
                __half* dst = g_Vt + ((size_t)bh * DK + d) * S + s0;
                #pragma unroll
                for (int sb = 0; sb < 4; sb++) {
                    int r = sb * 32 + lane;
                    float v = Cs[r * 136 + half * 64 + d] + bval;
                    dst[r] = __float2half(v);
                }
            }
        }
    }
};

struct EpiOut {
    const float* bias;
    float* out;
    __device__ void run(int /*z*/, int m0, int n0, int tid, const float* Cs) const {
        #pragma unroll
        for (int it = 0; it < 16; it++) {
            int idx = it * 256 + tid;
            int r = idx >> 5;
            int c4 = (idx & 31) * 4;
            float4 v = *reinterpret_cast<const float4*>(Cs + r * 136 + c4);
            int c = n0 + c4;
            v.x += bias[c]; v.y += bias[c + 1]; v.z += bias[c + 2]; v.w += bias[c + 3];
            *reinterpret_cast<float4*>(out + (size_t)(m0 + r) * E + c) = v;
        }
    }
};

// ---------------- cp.async 3-stage pipelined fp16 WMMA GEMM (BK=32, 2 CTAs/SM) ----
// AP=2: A split hi/lo (2 MMA passes). AP=1: A single fp16 (1 pass).
template<int BM, int BN, int AP, class Epi>
__global__ void __launch_bounds__(256, 2)
gemm_async(const __half* __restrict__ Ahi, const __half* __restrict__ Alo,
           const __half* __restrict__ Bs, int K, size_t sAz, size_t sBz, Epi epi)
{
    constexpr int LD = 40;
    constexpr int STG_BYTES = (AP * BM + BN) * LD * 2;
    constexpr int WM = 32, WN = BN / 2;
    constexpr int MI = WM / 16, NI = WN / 16;
    constexpr int LDC = BN + 8;

    extern __shared__ char smem[];
    const uint32_t sbase = smem_to_u32(smem);
    const int tid = threadIdx.x, wid = tid >> 5;
    const int z = blockIdx.z;
    const int m0 = blockIdx.y * BM, n0 = blockIdx.x * BN;
    const int wm0 = (wid & 3) * WM, wn0 = (wid >> 2) * WN;

    Ahi += (size_t)z * sAz;
    if (AP == 2) Alo += (size_t)z * sAz;
    Bs += (size_t)z * sBz;

    const int nchunks = K >> 5;

    auto stage = [&](int s, int ch) {
        const int k0 = ch << 5;
        const uint32_t sA = sbase + s * STG_BYTES;
        const uint32_t sB = sA + AP * BM * LD * 2;
        for (int u = tid; u < BM * 4; u += 256) {
            int r = u >> 2, g = u & 3;
            size_t gi = (size_t)(m0 + r) * K + k0 + g * 8;
            uint32_t so = sA + (uint32_t)(r * LD + g * 8) * 2;
            cp_async16(so, Ahi + gi);
            if (AP == 2) cp_async16(so + BM * LD * 2, Alo + gi);
        }
        for (int u = tid; u < BN * 4; u += 256) {
            int r = u >> 2, g = u & 3;
            size_t gi = (size_t)(n0 + r) * K + k0 + g * 8;
            cp_async16(sB + (uint32_t)(r * LD + g * 8) * 2, Bs + gi);
        }
        CP_COMMIT();
    };

    wmma::fragment<wmma::accumulator, 16, 16, 16, float> acc[MI][NI];
    #pragma unroll
    for (int mi = 0; mi < MI; mi++)
        #pragma unroll
        for (int ni = 0; ni < NI; ni++) wmma::fill_fragment(acc[mi][ni], 0.0f);

    stage(0, 0);
    if (nchunks > 1) stage(1, 1);
    for (int ch = 0; ch < nchunks; ch++) {
        if (ch + 2 < nchunks) { stage((ch + 2) % 3, ch + 2); CP_WAIT(2); }
        else if (ch + 1 < nchunks) { CP_WAIT(1); }
        else { CP_WAIT(0); }
        __syncthreads();

        const __half* As_hi =
            reinterpret_cast<const __half*>(smem + (ch % 3) * STG_BYTES);
        const __half* As_lo = As_hi + BM * LD;
        const __half* Bs_s  = As_hi + AP * BM * LD;

        #pragma unroll
        for (int ks = 0; ks < 2; ks++) {
            wmma::fragment<wmma::matrix_a, 16, 16, 16, __half, wmma::row_major> ah[MI], al[MI];
            wmma::fragment<wmma::matrix_b, 16, 16, 16, __half, wmma::col_major> bf[NI];
            #pragma unroll
            for (int mi = 0; mi < MI; mi++) {
                wmma::load_matrix_sync(ah[mi], As_hi + (wm0 + mi * 16) * LD + ks * 16, LD);
                if (AP == 2)
                    wmma::load_matrix_sync(al[mi], As_lo + (wm0 + mi * 16) * LD + ks * 16, LD);
            }
            #pragma unroll
            for (int ni = 0; ni < NI; ni++)
                wmma::load_matrix_sync(bf[ni], Bs_s + (wn0 + ni * 16) * LD + ks * 16, LD);
            #pragma unroll
            for (int mi = 0; mi < MI; mi++)
                #pragma unroll
                for (int ni = 0; ni < NI; ni++) {
                    wmma::mma_sync(acc[mi][ni], ah[mi], bf[ni], acc[mi][ni]);
                    if (AP == 2)
                        wmma::mma_sync(acc[mi][ni], al[mi], bf[ni], acc[mi][ni]);
                }
        }
        __syncthreads();
    }

    float* Cs = reinterpret_cast<float*>(smem);
    #pragma unroll
    for (int mi = 0; mi < MI; mi++)
        #pragma unroll
        for (int ni = 0; ni < NI; ni++)
            wmma::store_matrix_sync(Cs + (wm0 + mi * 16) * LDC + wn0 + ni * 16,
                                    acc[mi][ni], LDC, wmma::mem_row_major);
    __syncthreads();
    epi.run(z, m0, n0, tid, Cs);
}

// ---------------- STATS kernel: row sum of exp(l/8) (no max; data-safe) ------------
__global__ void __launch_bounds__(256, 2)
stats_kernel(const __half* __restrict__ Qhi, const __half* __restrict__ Qlo,
             const __half* __restrict__ Kp, float* __restrict__ ri)
{
    constexpr int LDQ = 72, LDK = 72, LDC = 72;
    constexpr int OFF_Q = 0;       // Qh 18432 + Ql 18432
    constexpr int OFF_K = 36864;   // 2 x 9216
    constexpr int OFF_C = 55296;   // 36864
    constexpr int OFF_S = 92160;   // 512 ; total 92672

    extern __shared__ char smem[];
    const uint32_t sbase = smem_to_u32(smem);
    const int tid = threadIdx.x, wid = tid >> 5;
    const int z = blockIdx.z, m0 = blockIdx.y * 128;
    const int wm0 = (wid & 3) * 32, wn0 = (wid >> 2) * 32;

    const __half* Qh_g = Qhi + ((size_t)z * S + m0) * DK;
    const __half* Ql_g = Qlo + ((size_t)z * S + m0) * DK;
    const __half* K_g  = Kp  + (size_t)z * S * DK;

    for (int u = tid; u < 128 * 8; u += 256) {
        int r = u >> 3, g = u & 7;
        cp_async16(sbase + OFF_Q + (uint32_t)(r * LDQ + g * 8) * 2, Qh_g + (size_t)r * DK + g * 8);
        cp_async16(sbase + OFF_Q + 18432 + (uint32_t)(r * LDQ + g * 8) * 2, Ql_g + (size_t)r * DK + g * 8);
    }
    CP_COMMIT();
    auto stage_k = [&](int s, int ch) {
        int k0 = ch << 6;
        for (int u = tid; u < 64 * 8; u += 256) {
            int r = u >> 3, g = u & 7;
            cp_async16(sbase + OFF_K + s * 9216 + (uint32_t)(r * LDK + g * 8) * 2,
                       K_g + (size_t)(k0 + r) * DK + g * 8);
        }
        CP_COMMIT();
    };
    stage_k(0, 0);

    float* sS = reinterpret_cast<float*>(smem + OFF_S);
    if (tid < 128) sS[tid] = 0.0f;

    const __half* sQh = reinterpret_cast<const __half*>(smem + OFF_Q);
    const __half* sQl = reinterpret_cast<const __half*>(smem + OFF_Q + 18432);
    float* Cs = reinterpret_cast<float*>(smem + OFF_C);

    for (int ch = 0; ch < 32; ch++) {
        if (ch + 1 < 32) { stage_k((ch + 1) & 1, ch + 1); CP_WAIT(1); }
        else             { CP_WAIT(0); }
        __syncthreads();
        const __half* sK = reinterpret_cast<const __half*>(smem + OFF_K + (ch & 1) * 9216);

        wmma::fragment<wmma::accumulator, 16, 16, 16, float> acc[2][2];
        #pragma unroll
        for (int mi = 0; mi < 2; mi++)
            #pragma unroll
            for (int ni = 0; ni < 2; ni++) wmma::fill_fragment(acc[mi][ni], 0.0f);

        #pragma unroll
        for (int ks = 0; ks < 4; ks++) {
            wmma::fragment<wmma::matrix_a, 16, 16, 16, __half, wmma::row_major> ah[2], al[2];
            wmma::fragment<wmma::matrix_b, 16, 16, 16, __half, wmma::col_major> bf[2];
            #pragma unroll
            for (int mi = 0; mi < 2; mi++) {
                wmma::load_matrix_sync(ah[mi], sQh + (wm0 + mi * 16) * LDQ + ks * 16, LDQ);
                wmma::load_matrix_sync(al[mi], sQl + (wm0 + mi * 16) * LDQ + ks * 16, LDQ);
            }
            #pragma unroll
            for (int ni = 0; ni < 2; ni++)
                wmma::load_matrix_sync(bf[ni], sK + (wn0 + ni * 16) * LDK + ks * 16, LDK);
            #pragma unroll
            for (int mi = 0; mi < 2; mi++)
                #pragma unroll
                for (int ni = 0; ni < 2; ni++) {
                    wmma::mma_sync(acc[mi][ni], ah[mi], bf[ni], acc[mi][ni]);
                    wmma::mma_sync(acc[mi][ni], al[mi], bf[ni], acc[mi][ni]);
                }
        }
        #pragma unroll
        for (int mi = 0; mi < 2; mi++)
            #pragma unroll
            for (int ni = 0; ni < 2; ni++)
                wmma::store_matrix_sync(Cs + (wm0 + mi * 16) * LDC + wn0 + ni * 16,
                                        acc[mi][ni], LDC, wmma::mem_row_major);
        __syncthreads();

        #pragma unroll
        for (int it = 0; it < 8; it++) {
            int idx = it * 256 + tid;
            int r = idx >> 4, c4 = (idx & 15) * 4;
            float4 v = *reinterpret_cast<const float4*>(Cs + r * LDC + c4);
            float ts = __expf(v.x * 0.125f) + __expf(v.y * 0.125f)
                     + __expf(v.z * 0.125f) + __expf(v.w * 0.125f);
            #pragma unroll
            for (int o = 8; o > 0; o >>= 1) ts += __shfl_xor_sync(0xFFFFFFFFu, ts, o);
            if ((tid & 15) == 0) sS[r] += ts;
        }
        __syncthreads();
    }

    if (tid < 128) {
        size_t ro = (size_t)z * S + m0 + tid;
        ri[ro] = 1.0f / sS[tid];
    }
}

// ---------------- PV2: recompute QK^T, softmax -> probs (only attn write), PV ------
// Ph row r is embedded at the start of Csf row r (stride 144 halves): the fp16
// overlay is strictly warp-local, so the __syncwarp read/write fence is sufficient.
__global__ void __launch_bounds__(256, 2)
pv2_kernel(float* __restrict__ attn, const float* __restrict__ ri,
           const __half* __restrict__ Qhi, const __half* __restrict__ Qlo,
           const __half* __restrict__ Kp, const __half* __restrict__ Vt)
{
    constexpr int LDQ = 72, LDK = 72, LDV = 72, LDCF = 72;
    constexpr int LDP = 144;        // halves; Ph row r starts at Csf row r
    constexpr int OFF_Q  = 0;       // 36864
    constexpr int OFF_K  = 36864;   // 2 x 9216
    constexpr int OFF_V  = 55296;   // 2 x 9216
    constexpr int OFF_C  = 73728;   // 36864 (fp32 logits / embedded fp16 probs)
    constexpr int OFF_RI = 110592;  // 512 ; total 111104

    extern __shared__ char smem[];
    const uint32_t sbase = smem_to_u32(smem);
    const int tid = threadIdx.x, wid = tid >> 5;
    const int z = blockIdx.z, m0 = blockIdx.y * 128;
    const int wm0 = (wid & 3) * 32, wn0 = (wid >> 2) * 32;

    const __half* Qh_g = Qhi + ((size_t)z * S + m0) * DK;
    const __half* Ql_g = Qlo + ((size_t)z * S + m0) * DK;
    const __half* K_g  = Kp  + (size_t)z * S * DK;
    const __half* V_g  = Vt  + (size_t)z * DK * S;
    float* attnZ = attn + (size_t)z * S * S;

    for (int u = tid; u < 128 * 8; u += 256) {
        int r = u >> 3, g = u & 7;
        cp_async16(sbase + OFF_Q + (uint32_t)(r * LDQ + g * 8) * 2, Qh_g + (size_t)r * DK + g * 8);
        cp_async16(sbase + OFF_Q + 18432 + (uint32_t)(r * LDQ + g * 8) * 2, Ql_g + (size_t)r * DK + g * 8);
    }
    CP_COMMIT();
    auto stage_kv = [&](int s, int ch) {
        int k0 = ch << 6;
        for (int u = tid; u < 64 * 8; u += 256) {
            int r = u >> 3, g = u & 7;
            cp_async16(sbase + OFF_K + s * 9216 + (uint32_t)(r * LDK + g * 8) * 2,
                       K_g + (size_t)(k0 + r) * DK + g * 8);
            cp_async16(sbase + OFF_V + s * 9216 + (uint32_t)(r * LDV + g * 8) * 2,
                       V_g + (size_t)r * S + k0 + g * 8);
        }
        CP_COMMIT();
    };
    stage_kv(0, 0);

    float* sRi = reinterpret_cast<float*>(smem + OFF_RI);
    if (tid < 128) sRi[tid] = ri[(size_t)z * S + m0 + tid];

    const __half* sQh = reinterpret_cast<const __half*>(smem + OFF_Q);
    const __half* sQl = reinterpret_cast<const __half*>(smem + OFF_Q + 18432);
    float* Csf = reinterpret_cast<float*>(smem + OFF_C);
    __half* PhB = reinterpret_cast<__half*>(smem + OFF_C);   // stride LDP=144 halves/row

    wmma::fragment<wmma::accumulator, 16, 16, 16, float> pacc[2][2];
    #pragma unroll
    for (int mi = 0; mi < 2; mi++)
        #pragma unroll
        for (int ni = 0; ni < 2; ni++) wmma::fill_fragment(pacc[mi][ni], 0.0f);

    for (int ch = 0; ch < 32; ch++) {
        __syncthreads();   // prev PV MMA complete: KV buf (ch+1)&1 and Csf/Ph reusable

        if (ch + 1 < 32) { stage_kv((ch + 1) & 1, ch + 1); CP_WAIT(1); }
        else             { CP_WAIT(0); }
        __syncthreads();   // KV[ch] visible to all threads

        const __half* sK = reinterpret_cast<const __half*>(smem + OFF_K + (ch & 1) * 9216);
        const __half* sV = reinterpret_cast<const __half*>(smem + OFF_V + (ch & 1) * 9216);

        // ---- QK^T recompute (identical arithmetic to stats_kernel) ----
        wmma::fragment<wmma::accumulator, 16, 16, 16, float> qacc[2][2];
        #pragma unroll
        for (int mi = 0; mi < 2; mi++)
            #pragma unroll
            for (int ni = 0; ni < 2; ni++) wmma::fill_fragment(qacc[mi][ni], 0.0f);
        #pragma unroll
        for (int ks = 0; ks < 4; ks++) {
            wmma::fragment<wmma::matrix_a, 16, 16, 16, __half, wmma::row_major> ah[2], al[2];
            wmma::fragment<wmma::matrix_b, 16, 16, 16, __half, wmma::col_major> bf[2];
            #pragma unroll
            for (int mi = 0; mi < 2; mi++) {
                wmma::load_matrix_sync(ah[mi], sQh + (wm0 + mi * 16) * LDQ + ks * 16, LDQ);
                wmma::load_matrix_sync(al[mi], sQl + (wm0 + mi * 16) * LDQ + ks * 16, LDQ);
            }
            #pragma unroll
            for (int ni = 0; ni < 2; ni++)
                wmma::load_matrix_sync(bf[ni], sK + (wn0 + ni * 16) * LDK + ks * 16, LDK);
            #pragma unroll
            for (int mi = 0; mi < 2; mi++)
                #pragma unroll
                for (int ni = 0; ni < 2; ni++) {
                    wmma::mma_sync(qacc[mi][ni], ah[mi], bf[ni], qacc[mi][ni]);
                    wmma::mma_sync(qacc[mi][ni], al[mi], bf[ni], qacc[mi][ni]);
                }
        }
        #pragma unroll
        for (int mi = 0; mi < 2; mi++)
            #pragma unroll
            for (int ni = 0; ni < 2; ni++)
                wmma::store_matrix_sync(Csf + (wm0 + mi * 16) * LDCF + wn0 + ni * 16,
                                        qacc[mi][ni], LDCF, wmma::mem_row_major);
        __syncthreads();

        // ---- transform: exp/Σ, write probs to attn, warp-local fp16 pack ----
        const int n0 = ch << 6;
        #pragma unroll
        for (int it = 0; it < 8; it++) {
            int idx = it * 256 + tid;
            int r = idx >> 4, c4 = (idx & 15) * 4;   // row r handled by half-warp (warp-local)
            float4 v = *reinterpret_cast<const float4*>(Csf + r * LDCF + c4);
            float rv = sRi[r];
            float4 p;
            p.x = __expf(v.x * 0.125f) * rv;
            p.y = __expf(v.y * 0.125f) * rv;
            p.z = __expf(v.z * 0.125f) * rv;
            p.w = __expf(v.w * 0.125f) * rv;
            *reinterpret_cast<float4*>(attnZ + (size_t)(m0 + r) * S + n0 + c4) = p;
            __syncwarp();   // warp finished reading its rows before fp16 overlay
            *reinterpret_cast<uint2*>(PhB + r * LDP + c4) =
                make_uint2(pack2h(p.x, p.y), pack2h(p.z, p.w));
        }
        __syncthreads();

        // ---- PV MMA, single pass on fp16 probs ----
        #pragma unroll
        for (int ks = 0; ks < 4; ks++) {
            wmma::fragment<wmma::matrix_a, 16, 16, 16, __half, wmma::row_major> af[2];
            wmma::fragment<wmma::matrix_b, 16, 16, 16, __half, wmma::col_major> bf[2];
            #pragma unroll
            for (int mi = 0; mi < 2; mi++)
                wmma::load_matrix_sync(af[mi], PhB + (wm0 + mi * 16) * LDP + ks * 16, LDP);
            #pragma unroll
            for (int ni = 0; ni < 2; ni++)
                wmma::load_matrix_sync(bf[ni], sV + (wn0 + ni * 16) * LDV + ks * 16, LDV);
            #pragma unroll
            for (int mi = 0; mi < 2; mi++)
                #pragma unroll
                for (int ni = 0; ni < 2; ni++)
                    wmma::mma_sync(pacc[mi][ni], af[mi], bf[ni], pacc[mi][ni]);
        }
    }
    __syncthreads();

    // ---- epilogue: values -> g_vals single fp16 [B,S,E] ----
    #pragma unroll
    for (int mi = 0; mi < 2; mi++)
        #pragma unroll
        for (int ni = 0; ni < 2; ni++)
            wmma::store_matrix_sync(Csf + (wm0 + mi * 16) * 72 + wn0 + ni * 16,
                                    pacc[mi][ni], 72, wmma::mem_row_major);
    __syncthreads();

    int b = z >> 4, h = z & 15;
    #pragma unroll
    for (int it = 0; it < 8; it++) {
        int idx = it * 256 + tid;
        int r = idx >> 4;
        int c4 = (idx & 15) * 4;
        float4 v = *reinterpret_cast<const float4*>(Csf + r * 72 + c4);
        size_t off = (size_t)(b * S + m0 + r) * E + h * DK + c4;
        *reinterpret_cast<uint2*>(g_vals + off) =
            make_uint2(pack2h(v.x, v.y), pack2h(v.z, v.w));
    }
}

// ---------------- pre-kernels ----------------
__global__ void __launch_bounds__(256)
split_kernel(const float* __restrict__ src, __half* __restrict__ dh,
             __half* __restrict__ dl, size_t n)
{
    size_t i = ((size_t)blockIdx.x * 256 + threadIdx.x) * 4;
    if (i >= n) return;
    float4 v = *reinterpret_cast<const float4*>(src + i);
    uint32_t h0, l0, h1, l1;
    pack_split2h(v.x, v.y, h0, l0);
    pack_split2h(v.z, v.w, h1, l1);
    *reinterpret_cast<uint2*>(dh + i) = make_uint2(h0, h1);
    *reinterpret_cast<uint2*>(dl + i) = make_uint2(l0, l1);
}

__global__ void __launch_bounds__(256)
transpose_h(const float* __restrict__ W, __half* __restrict__ Th, int R, int C)
{
    __shared__ float t[32][33];
    int c0 = blockIdx.x * 32, r0 = blockIdx.y * 32;
    int tx = threadIdx.x & 31, ty = threadIdx.x >> 5;
    for (int j = ty; j < 32; j += 8)
        t[j][tx] = W[(size_t)(r0 + j) * C + c0 + tx];
    __syncthreads();
    for (int j = ty; j < 32; j += 8)
        Th[(size_t)(c0 + j) * R + r0 + tx] = __float2half(t[tx][j]);
}

// ---------------- launch ----------------
extern "C" void kernel_launch(void* const* d_in, const int* /*in_sizes*/, int /*n_in*/,
                              void* d_out, int /*out_size*/)
{
    const float* x    = (const float*)d_in[0];
    const float* Wqkv = (const float*)d_in[1];
    const float* bqkv = (const float*)d_in[2];
    const float* Wout = (const float*)d_in[3];
    const float* bout = (const float*)d_in[4];

    float* out  = (float*)d_out;
    float* attn = out + (size_t)M_TOK * E;

    __half *xhi, *xlo, *Wq, *Wo, *Qhi, *Qlo, *Kp, *Vt, *Vl;
    float *ri;
    cudaGetSymbolAddress((void**)&xhi, g_xhi);
    cudaGetSymbolAddress((void**)&xlo, g_xlo);
    cudaGetSymbolAddress((void**)&Wq,  g_Wqt);
    cudaGetSymbolAddress((void**)&Wo,  g_Wot);
    cudaGetSymbolAddress((void**)&Qhi, g_Qhi);
    cudaGetSymbolAddress((void**)&Qlo, g_Qlo);
    cudaGetSymbolAddress((void**)&Kp,  g_K);
    cudaGetSymbolAddress((void**)&Vt,  g_Vt);
    cudaGetSymbolAddress((void**)&Vl,  g_vals);
    cudaGetSymbolAddress((void**)&ri,  g_ri);

    // QKV: 3 stages * 30720 = 92160 (> Cs 69632). Out: max(3*20480, 69632) = 69632.
    constexpr int SM_QKV  = 92160;
    constexpr int SM_OUT  = 69632;
    constexpr int SM_STATS = 92672;
    constexpr int SM_PV2   = 111104;
    cudaFuncSetAttribute(gemm_async<128, 128, 2, EpiQKV>,
                         cudaFuncAttributeMaxDynamicSharedMemorySize, SM_QKV);
    cudaFuncSetAttribute(gemm_async<128, 128, 1, EpiOut>,
                         cudaFuncAttributeMaxDynamicSharedMemorySize, SM_OUT);
    cudaFuncSetAttribute(stats_kernel,
                         cudaFuncAttributeMaxDynamicSharedMemorySize, SM_STATS);
    cudaFuncSetAttribute(pv2_kernel,
                         cudaFuncAttributeMaxDynamicSharedMemorySize, SM_PV2);

    // 0) operand prep
    transpose_h<<<dim3(3 * E / 32, E / 32), 256>>>(Wqkv, Wq, E, 3 * E);
    transpose_h<<<dim3(E / 32, E / 32), 256>>>(Wout, Wo, E, E);
    split_kernel<<<(unsigned)((size_t)M_TOK * E / 4 / 256), 256>>>(x, xhi, xlo, (size_t)M_TOK * E);

    // 1) QKV projection (A = x split, 2-pass, 3-stage pipeline)
    gemm_async<128, 128, 2, EpiQKV><<<dim3(3 * E / 128, M_TOK / 128, 1), 256, SM_QKV>>>(
        xhi, xlo, Wq, E, 0, 0, EpiQKV{bqkv});

    // 2) stats: per-row 1/sum(exp(l/8))   (no max subtraction; data-safe)
    stats_kernel<<<dim3(1, S / 128, BH), 256, SM_STATS>>>(Qhi, Qlo, Kp, ri);

    // 3) PV2: recompute logits, probs -> attn (single pass), PV (probs single fp16)
    pv2_kernel<<<dim3(1, S / 128, BH), 256, SM_PV2>>>(attn, ri, Qhi, Qlo, Kp, Vt);

    // 4) output projection (A = vals single fp16, 1-pass, 3-stage pipeline)
    gemm_async<128, 128, 1, EpiOut><<<dim3(E / 128, M_TOK / 128, 1), 256, SM_OUT>>>(
        Vl, nullptr, Wo, E, 0, 0, EpiOut{bout, out});
}

// round 16
// speedup vs baseline: 1.5257x; 1.0139x over previous
#include <cuda_runtime.h>
#include <cuda_fp16.h>
#include <mma.h>
#include <cstdint>
#include <cstddef>
#include <math_constants.h>

using namespace nvcuda;

// Problem constants
static constexpr int B  = 4;
static constexpr int S  = 2048;
static constexpr int E  = 1024;
static constexpr int H  = 16;
static constexpr int DK = 64;
static constexpr int BH = B * H;      // 64
static constexpr int M_TOK = B * S;   // 8192

// ---------------- scratch (device globals; no cudaMalloc allowed) ----------------
__device__ __half g_xhi[(size_t)M_TOK * E], g_xlo[(size_t)M_TOK * E];
__device__ __half g_Wqt[(size_t)3 * E * E];
__device__ __half g_Wot[(size_t)E * E];
__device__ __half g_Qhi[(size_t)BH * S * DK], g_Qlo[(size_t)BH * S * DK];
__device__ __half g_K  [(size_t)BH * S * DK];
__device__ __half g_Vt [(size_t)BH * DK * S];
__device__ __half g_vals[(size_t)M_TOK * E];
__device__ float g_ri[(size_t)BH * S];

// ---------------- helpers ----------------
__device__ __forceinline__ uint32_t smem_to_u32(const void* p) {
    uint32_t a;
    asm("{ .reg .u64 t; cvta.to.shared.u64 t, %1; cvt.u32.u64 %0, t; }" : "=r"(a) : "l"(p));
    return a;
}
__device__ __forceinline__ void cp_async16(uint32_t dst, const void* src) {
    asm volatile("cp.async.cg.shared.global [%0], [%1], 16;" :: "r"(dst), "l"(src));
}
#define CP_COMMIT() asm volatile("cp.async.commit_group;" ::: "memory")
#define CP_WAIT(N)  asm volatile("cp.async.wait_group %0;" :: "n"(N) : "memory")

__device__ __forceinline__ void stcs4(float* p, float4 v) {
    asm volatile("st.global.cs.v4.f32 [%0], {%1,%2,%3,%4};"
                 :: "l"(p), "f"(v.x), "f"(v.y), "f"(v.z), "f"(v.w) : "memory");
}
__device__ __forceinline__ void stcs2u(void* p, uint2 v) {
    asm volatile("st.global.cs.v2.u32 [%0], {%1,%2};"
                 :: "l"(p), "r"(v.x), "r"(v.y) : "memory");
}

__device__ __forceinline__ uint32_t pack2h(float a, float b) {
    __half2 p(__float2half(a), __float2half(b));
    return *reinterpret_cast<uint32_t*>(&p);
}
__device__ __forceinline__ void split2h(float v, __half& h, __half& l) {
    h = __float2half(v);
    l = __float2half(v - __half2float(h));
}
__device__ __forceinline__ void pack_split2h(float a, float b, uint32_t& hi, uint32_t& lo) {
    __half ha, la, hb, lb;
    split2h(a, ha, la); split2h(b, hb, lb);
    __half2 Hp(ha, hb), Lp(la, lb);
    hi = *reinterpret_cast<uint32_t*>(&Hp);
    lo = *reinterpret_cast<uint32_t*>(&Lp);
}

// ---------------- epilogues for projection GEMMs (BN=128, LDC=136) ----------------
struct EpiQKV {
    const float* bias;
    __device__ void run(int /*z*/, int m0, int n0, int tid, const float* Cs) const {
        #pragma unroll
        for (int it = 0; it < 16; it++) {
            int idx = it * 256 + tid;
            int r = idx >> 5;
            int c4 = (idx & 31) * 4;
            int c = n0 + c4;
            int h = c / 192, cc = c - h * 192;
            int t = cc >> 6, d0 = cc & 63;
            if (t == 2) continue;   // V handled by transposed path below
            float4 v = *reinterpret_cast<const float4*>(Cs + r * 136 + c4);
            v.x += bias[c]; v.y += bias[c + 1]; v.z += bias[c + 2]; v.w += bias[c + 3];
            int gr = m0 + r;
            int b = gr >> 11, s = gr & 2047;
            int bh = b * H + h;
            if (t == 1) {
                size_t off = ((size_t)bh * S + s) * DK + d0;
                *reinterpret_cast<uint2*>(g_K + off) =
                    make_uint2(pack2h(v.x, v.y), pack2h(v.z, v.w));
            } else {
                uint32_t h0, l0, h1, l1;
                pack_split2h(v.x, v.y, h0, l0);
                pack_split2h(v.z, v.w, h1, l1);
                size_t off = ((size_t)bh * S + s) * DK + d0;
                *reinterpret_cast<uint2*>(g_Qhi + off) = make_uint2(h0, h1);
                *reinterpret_cast<uint2*>(g_Qlo + off) = make_uint2(l0, l1);
            }
        }
        // ---- V columns: transposed, coalesced along s ----
        const int wid = tid >> 5, lane = tid & 31;
        const int b = m0 >> 11, s0 = m0 & 2047;
        #pragma unroll
        for (int half = 0; half < 2; half++) {
            int cbase = n0 + half * 64;
            int h = cbase / 192, cc = cbase - h * 192;
            if ((cc >> 6) != 2) continue;
            int bh = b * H + h;
            #pragma unroll
            for (int dd = 0; dd < 8; dd++) {
                int d = wid * 8 + dd;
                float bval = bias[cbase + d];
                __half* dst = g_Vt + ((size_t)bh * DK + d) * S + s0;
                #pragma unroll
                for (int sb = 0; sb < 4; sb++) {
                    int r = sb * 32 + lane;
                    float v = Cs[r * 136 + half * 64 + d] + bval;
                    dst[r] = __float2half(v);
                }
            }
        }
    }
};

struct EpiOut {
    const float* bias;
    float* out;
    __device__ void run(int /*z*/, int m0, int n0, int tid, const float* Cs) const {
        #pragma unroll
        for (int it = 0; it < 16; it++) {
            int idx = it * 256 + tid;
            int r = idx >> 5;
            int c4 = (idx & 31) * 4;
            float4 v = *reinterpret_cast<const float4*>(Cs + r * 136 + c4);
            int c = n0 + c4;
            v.x += bias[c]; v.y += bias[c + 1]; v.z += bias[c + 2]; v.w += bias[c + 3];
            stcs4(out + (size_t)(m0 + r) * E + c, v);
        }
    }
};

// ---------------- cp.async 3-stage pipelined fp16 WMMA GEMM (BK=32, 2 CTAs/SM) ----
template<int BM, int BN, int AP, class Epi>
__global__ void __launch_bounds__(256, 2)
gemm_async(const __half* __restrict__ Ahi, const __half* __restrict__ Alo,
           const __half* __restrict__ Bs, int K, size_t sAz, size_t sBz, Epi epi)
{
    constexpr int LD = 40;
    constexpr int STG_BYTES = (AP * BM + BN) * LD * 2;
    constexpr int WM = 32, WN = BN / 2;
    constexpr int MI = WM / 16, NI = WN / 16;
    constexpr int LDC = BN + 8;

    extern __shared__ char smem[];
    const uint32_t sbase = smem_to_u32(smem);
    const int tid = threadIdx.x, wid = tid >> 5;
    const int z = blockIdx.z;
    const int m0 = blockIdx.y * BM, n0 = blockIdx.x * BN;
    const int wm0 = (wid & 3) * WM, wn0 = (wid >> 2) * WN;

    Ahi += (size_t)z * sAz;
    if (AP == 2) Alo += (size_t)z * sAz;
    Bs += (size_t)z * sBz;

    const int nchunks = K >> 5;

    auto stage = [&](int s, int ch) {
        const int k0 = ch << 5;
        const uint32_t sA = sbase + s * STG_BYTES;
        const uint32_t sB = sA + AP * BM * LD * 2;
        for (int u = tid; u < BM * 4; u += 256) {
            int r = u >> 2, g = u & 3;
            size_t gi = (size_t)(m0 + r) * K + k0 + g * 8;
            uint32_t so = sA + (uint32_t)(r * LD + g * 8) * 2;
            cp_async16(so, Ahi + gi);
            if (AP == 2) cp_async16(so + BM * LD * 2, Alo + gi);
        }
        for (int u = tid; u < BN * 4; u += 256) {
            int r = u >> 2, g = u & 3;
            size_t gi = (size_t)(n0 + r) * K + k0 + g * 8;
            cp_async16(sB + (uint32_t)(r * LD + g * 8) * 2, Bs + gi);
        }
        CP_COMMIT();
    };

    wmma::fragment<wmma::accumulator, 16, 16, 16, float> acc[MI][NI];
    #pragma unroll
    for (int mi = 0; mi < MI; mi++)
        #pragma unroll
        for (int ni = 0; ni < NI; ni++) wmma::fill_fragment(acc[mi][ni], 0.0f);

    stage(0, 0);
    if (nchunks > 1) stage(1, 1);
    for (int ch = 0; ch < nchunks; ch++) {
        if (ch + 2 < nchunks) { stage((ch + 2) % 3, ch + 2); CP_WAIT(2); }
        else if (ch + 1 < nchunks) { CP_WAIT(1); }
        else { CP_WAIT(0); }
        __syncthreads();

        const __half* As_hi =
            reinterpret_cast<const __half*>(smem + (ch % 3) * STG_BYTES);
        const __half* As_lo = As_hi + BM * LD;
        const __half* Bs_s  = As_hi + AP * BM * LD;

        #pragma unroll
        for (int ks = 0; ks < 2; ks++) {
            wmma::fragment<wmma::matrix_a, 16, 16, 16, __half, wmma::row_major> ah[MI], al[MI];
            wmma::fragment<wmma::matrix_b, 16, 16, 16, __half, wmma::col_major> bf[NI];
            #pragma unroll
            for (int mi = 0; mi < MI; mi++) {
                wmma::load_matrix_sync(ah[mi], As_hi + (wm0 + mi * 16) * LD + ks * 16, LD);
                if (AP == 2)
                    wmma::load_matrix_sync(al[mi], As_lo + (wm0 + mi * 16) * LD + ks * 16, LD);
            }
            #pragma unroll
            for (int ni = 0; ni < NI; ni++)
                wmma::load_matrix_sync(bf[ni], Bs_s + (wn0 + ni * 16) * LD + ks * 16, LD);
            #pragma unroll
            for (int mi = 0; mi < MI; mi++)
                #pragma unroll
                for (int ni = 0; ni < NI; ni++) {
                    wmma::mma_sync(acc[mi][ni], ah[mi], bf[ni], acc[mi][ni]);
                    if (AP == 2)
                        wmma::mma_sync(acc[mi][ni], al[mi], bf[ni], acc[mi][ni]);
                }
        }
        __syncthreads();
    }

    float* Cs = reinterpret_cast<float*>(smem);
    #pragma unroll
    for (int mi = 0; mi < MI; mi++)
        #pragma unroll
        for (int ni = 0; ni < NI; ni++)
            wmma::store_matrix_sync(Cs + (wm0 + mi * 16) * LDC + wn0 + ni * 16,
                                    acc[mi][ni], LDC, wmma::mem_row_major);
    __syncthreads();
    epi.run(z, m0, n0, tid, Cs);
}

// ---------------- STATS: Σexp(l/8) per row; warp-local epilogue, 3-stage K ---------
__global__ void __launch_bounds__(256, 2)
stats_kernel(const __half* __restrict__ Qhi, const __half* __restrict__ Qlo,
             const __half* __restrict__ Kp, float* __restrict__ ri)
{
    constexpr int LDQ = 72, LDK = 72, LDC = 72;
    constexpr int OFF_Q  = 0;       // 36864
    constexpr int OFF_K  = 36864;   // 3 x 9216 = 27648
    constexpr int OFF_C  = 64512;   // 36864
    constexpr int OFF_S2 = 101376;  // 128*2*4 = 1024 ; total 102400

    extern __shared__ char smem[];
    const uint32_t sbase = smem_to_u32(smem);
    const int tid = threadIdx.x, wid = tid >> 5, lane = tid & 31;
    const int z = blockIdx.z, m0 = blockIdx.y * 128;
    const int wm0 = (wid & 3) * 32, wn0 = (wid >> 2) * 32;
    const int whalf = wid >> 2;

    const __half* Qh_g = Qhi + ((size_t)z * S + m0) * DK;
    const __half* Ql_g = Qlo + ((size_t)z * S + m0) * DK;
    const __half* K_g  = Kp  + (size_t)z * S * DK;

    for (int u = tid; u < 128 * 8; u += 256) {
        int r = u >> 3, g = u & 7;
        cp_async16(sbase + OFF_Q + (uint32_t)(r * LDQ + g * 8) * 2, Qh_g + (size_t)r * DK + g * 8);
        cp_async16(sbase + OFF_Q + 18432 + (uint32_t)(r * LDQ + g * 8) * 2, Ql_g + (size_t)r * DK + g * 8);
    }
    CP_COMMIT();
    auto stage_k = [&](int s, int ch) {
        int k0 = ch << 6;
        for (int u = tid; u < 64 * 8; u += 256) {
            int r = u >> 3, g = u & 7;
            cp_async16(sbase + OFF_K + s * 9216 + (uint32_t)(r * LDK + g * 8) * 2,
                       K_g + (size_t)(k0 + r) * DK + g * 8);
        }
        CP_COMMIT();
    };
    stage_k(0, 0);
    stage_k(1, 1);

    float* sS2 = reinterpret_cast<float*>(smem + OFF_S2);
    if (tid < 256) { sS2[tid] = 0.0f; }

    const __half* sQh = reinterpret_cast<const __half*>(smem + OFF_Q);
    const __half* sQl = reinterpret_cast<const __half*>(smem + OFF_Q + 18432);
    float* Cs = reinterpret_cast<float*>(smem + OFF_C);

    for (int ch = 0; ch < 32; ch++) {
        __syncthreads();   // prev MMA done: stage buffer (ch+2)%3 reusable
        if (ch + 2 < 32) { stage_k((ch + 2) % 3, ch + 2); CP_WAIT(2); }
        else if (ch + 1 < 32) { CP_WAIT(1); }
        else { CP_WAIT(0); }
        __syncthreads();   // K[ch] visible
        const __half* sK = reinterpret_cast<const __half*>(smem + OFF_K + (ch % 3) * 9216);

        wmma::fragment<wmma::accumulator, 16, 16, 16, float> acc[2][2];
        #pragma unroll
        for (int mi = 0; mi < 2; mi++)
            #pragma unroll
            for (int ni = 0; ni < 2; ni++) wmma::fill_fragment(acc[mi][ni], 0.0f);

        #pragma unroll
        for (int ks = 0; ks < 4; ks++) {
            wmma::fragment<wmma::matrix_a, 16, 16, 16, __half, wmma::row_major> ah[2], al[2];
            wmma::fragment<wmma::matrix_b, 16, 16, 16, __half, wmma::col_major> bf[2];
            #pragma unroll
            for (int mi = 0; mi < 2; mi++) {
                wmma::load_matrix_sync(ah[mi], sQh + (wm0 + mi * 16) * LDQ + ks * 16, LDQ);
                wmma::load_matrix_sync(al[mi], sQl + (wm0 + mi * 16) * LDQ + ks * 16, LDQ);
            }
            #pragma unroll
            for (int ni = 0; ni < 2; ni++)
                wmma::load_matrix_sync(bf[ni], sK + (wn0 + ni * 16) * LDK + ks * 16, LDK);
            #pragma unroll
            for (int mi = 0; mi < 2; mi++)
                #pragma unroll
                for (int ni = 0; ni < 2; ni++) {
                    wmma::mma_sync(acc[mi][ni], ah[mi], bf[ni], acc[mi][ni]);
                    wmma::mma_sync(acc[mi][ni], al[mi], bf[ni], acc[mi][ni]);
                }
        }
        // warp-local: store own 32x32 tile, reduce own tile (no block barrier)
        #pragma unroll
        for (int mi = 0; mi < 2; mi++)
            #pragma unroll
            for (int ni = 0; ni < 2; ni++)
                wmma::store_matrix_sync(Cs + (wm0 + mi * 16) * LDC + wn0 + ni * 16,
                                        acc[mi][ni], LDC, wmma::mem_row_major);
        __syncwarp();
        #pragma unroll
        for (int j = 0; j < 8; j++) {
            int r = wm0 + j * 4 + (lane >> 3);
            int c4 = wn0 + (lane & 7) * 4;
            float4 v = *reinterpret_cast<const float4*>(Cs + r * LDC + c4);
            float ts = __expf(v.x * 0.125f) + __expf(v.y * 0.125f)
                     + __expf(v.z * 0.125f) + __expf(v.w * 0.125f);
            #pragma unroll
            for (int o = 4; o > 0; o >>= 1) ts += __shfl_xor_sync(0xFFFFFFFFu, ts, o);
            if ((lane & 7) == 0) sS2[r * 2 + whalf] += ts;
        }
        __syncwarp();   // own-tile reduce done before next chunk's store overwrites
    }
    __syncthreads();

    if (tid < 128) {
        size_t ro = (size_t)z * S + m0 + tid;
        ri[ro] = 1.0f / (sS2[tid * 2] + sS2[tid * 2 + 1]);
    }
}

// ---------------- PV2: recompute QK^T, softmax -> probs (only attn write), PV ------
__global__ void __launch_bounds__(256, 2)
pv2_kernel(float* __restrict__ attn, const float* __restrict__ ri,
           const __half* __restrict__ Qhi, const __half* __restrict__ Qlo,
           const __half* __restrict__ Kp, const __half* __restrict__ Vt)
{
    constexpr int LDQ = 72, LDK = 72, LDV = 72, LDCF = 72;
    constexpr int LDP = 144;        // halves; Ph row r starts at Csf row r
    constexpr int OFF_Q  = 0;       // 36864
    constexpr int OFF_K  = 36864;   // 2 x 9216
    constexpr int OFF_V  = 55296;   // 2 x 9216
    constexpr int OFF_C  = 73728;   // 36864
    constexpr int OFF_RI = 110592;  // 512 ; total 111104

    extern __shared__ char smem[];
    const uint32_t sbase = smem_to_u32(smem);
    const int tid = threadIdx.x, wid = tid >> 5;
    const int z = blockIdx.z, m0 = blockIdx.y * 128;
    const int wm0 = (wid & 3) * 32, wn0 = (wid >> 2) * 32;

    const __half* Qh_g = Qhi + ((size_t)z * S + m0) * DK;
    const __half* Ql_g = Qlo + ((size_t)z * S + m0) * DK;
    const __half* K_g  = Kp  + (size_t)z * S * DK;
    const __half* V_g  = Vt  + (size_t)z * DK * S;
    float* attnZ = attn + (size_t)z * S * S;

    for (int u = tid; u < 128 * 8; u += 256) {
        int r = u >> 3, g = u & 7;
        cp_async16(sbase + OFF_Q + (uint32_t)(r * LDQ + g * 8) * 2, Qh_g + (size_t)r * DK + g * 8);
        cp_async16(sbase + OFF_Q + 18432 + (uint32_t)(r * LDQ + g * 8) * 2, Ql_g + (size_t)r * DK + g * 8);
    }
    CP_COMMIT();
    auto stage_kv = [&](int s, int ch) {
        int k0 = ch << 6;
        for (int u = tid; u < 64 * 8; u += 256) {
            int r = u >> 3, g = u & 7;
            cp_async16(sbase + OFF_K + s * 9216 + (uint32_t)(r * LDK + g * 8) * 2,
                       K_g + (size_t)(k0 + r) * DK + g * 8);
            cp_async16(sbase + OFF_V + s * 9216 + (uint32_t)(r * LDV + g * 8) * 2,
                       V_g + (size_t)r * S + k0 + g * 8);
        }
        CP_COMMIT();
    };
    stage_kv(0, 0);

    float* sRi = reinterpret_cast<float*>(smem + OFF_RI);
    if (tid < 128) sRi[tid] = ri[(size_t)z * S + m0 + tid];

    const __half* sQh = reinterpret_cast<const __half*>(smem + OFF_Q);
    const __half* sQl = reinterpret_cast<const __half*>(smem + OFF_Q + 18432);
    float* Csf = reinterpret_cast<float*>(smem + OFF_C);
    __half* PhB = reinterpret_cast<__half*>(smem + OFF_C);

    wmma::fragment<wmma::accumulator, 16, 16, 16, float> pacc[2][2];
    #pragma unroll
    for (int mi = 0; mi < 2; mi++)
        #pragma unroll
        for (int ni = 0; ni < 2; ni++) wmma::fill_fragment(pacc[mi][ni], 0.0f);

    for (int ch = 0; ch < 32; ch++) {
        __syncthreads();

        if (ch + 1 < 32) { stage_kv((ch + 1) & 1, ch + 1); CP_WAIT(1); }
        else             { CP_WAIT(0); }
        __syncthreads();

        const __half* sK = reinterpret_cast<const __half*>(smem + OFF_K + (ch & 1) * 9216);
        const __half* sV = reinterpret_cast<const __half*>(smem + OFF_V + (ch & 1) * 9216);

        // ---- QK^T recompute (identical arithmetic to stats_kernel) ----
        wmma::fragment<wmma::accumulator, 16, 16, 16, float> qacc[2][2];
        #pragma unroll
        for (int mi = 0; mi < 2; mi++)
            #pragma unroll
            for (int ni = 0; ni < 2; ni++) wmma::fill_fragment(qacc[mi][ni], 0.0f);
        #pragma unroll
        for (int ks = 0; ks < 4; ks++) {
            wmma::fragment<wmma::matrix_a, 16, 16, 16, __half, wmma::row_major> ah[2], al[2];
            wmma::fragment<wmma::matrix_b, 16, 16, 16, __half, wmma::col_major> bf[2];
            #pragma unroll
            for (int mi = 0; mi < 2; mi++) {
                wmma::load_matrix_sync(ah[mi], sQh + (wm0 + mi * 16) * LDQ + ks * 16, LDQ);
                wmma::load_matrix_sync(al[mi], sQl + (wm0 + mi * 16) * LDQ + ks * 16, LDQ);
            }
            #pragma unroll
            for (int ni = 0; ni < 2; ni++)
                wmma::load_matrix_sync(bf[ni], sK + (wn0 + ni * 16) * LDK + ks * 16, LDK);
            #pragma unroll
            for (int mi = 0; mi < 2; mi++)
                #pragma unroll
                for (int ni = 0; ni < 2; ni++) {
                    wmma::mma_sync(qacc[mi][ni], ah[mi], bf[ni], qacc[mi][ni]);
                    wmma::mma_sync(qacc[mi][ni], al[mi], bf[ni], qacc[mi][ni]);
                }
        }
        #pragma unroll
        for (int mi = 0; mi < 2; mi++)
            #pragma unroll
            for (int ni = 0; ni < 2; ni++)
                wmma::store_matrix_sync(Csf + (wm0 + mi * 16) * LDCF + wn0 + ni * 16,
                                        qacc[mi][ni], LDCF, wmma::mem_row_major);
        __syncthreads();

        // ---- transform: exp/Σ, probs -> attn (streaming), warp-local fp16 pack ----
        const int n0 = ch << 6;
        #pragma unroll
        for (int it = 0; it < 8; it++) {
            int idx = it * 256 + tid;
            int r = idx >> 4, c4 = (idx & 15) * 4;
            float4 v = *reinterpret_cast<const float4*>(Csf + r * LDCF + c4);
            float rv = sRi[r];
            float4 p;
            p.x = __expf(v.x * 0.125f) * rv;
            p.y = __expf(v.y * 0.125f) * rv;
            p.z = __expf(v.z * 0.125f) * rv;
            p.w = __expf(v.w * 0.125f) * rv;
            stcs4(attnZ + (size_t)(m0 + r) * S + n0 + c4, p);
            __syncwarp();
            *reinterpret_cast<uint2*>(PhB + r * LDP + c4) =
                make_uint2(pack2h(p.x, p.y), pack2h(p.z, p.w));
        }
        __syncthreads();

        // ---- PV MMA, single pass on fp16 probs ----
        #pragma unroll
        for (int ks = 0; ks < 4; ks++) {
            wmma::fragment<wmma::matrix_a, 16, 16, 16, __half, wmma::row_major> af[2];
            wmma::fragment<wmma::matrix_b, 16, 16, 16, __half, wmma::col_major> bf[2];
            #pragma unroll
            for (int mi = 0; mi < 2; mi++)
                wmma::load_matrix_sync(af[mi], PhB + (wm0 + mi * 16) * LDP + ks * 16, LDP);
            #pragma unroll
            for (int ni = 0; ni < 2; ni++)
                wmma::load_matrix_sync(bf[ni], sV + (wn0 + ni * 16) * LDV + ks * 16, LDV);
            #pragma unroll
            for (int mi = 0; mi < 2; mi++)
                #pragma unroll
                for (int ni = 0; ni < 2; ni++)
                    wmma::mma_sync(pacc[mi][ni], af[mi], bf[ni], pacc[mi][ni]);
        }
    }
    __syncthreads();

    // ---- epilogue: values -> g_vals single fp16 [B,S,E] ----
    #pragma unroll
    for (int mi = 0; mi < 2; mi++)
        #pragma unroll
        for (int ni = 0; ni < 2; ni++)
            wmma::store_matrix_sync(Csf + (wm0 + mi * 16) * 72 + wn0 + ni * 16,
                                    pacc[mi][ni], 72, wmma::mem_row_major);
    __syncthreads();

    int b = z >> 4, h = z & 15;
    #pragma unroll
    for (int it = 0; it < 8; it++) {
        int idx = it * 256 + tid;
        int r = idx >> 4;
        int c4 = (idx & 15) * 4;
        float4 v = *reinterpret_cast<const float4*>(Csf + r * 72 + c4);
        size_t off = (size_t)(b * S + m0 + r) * E + h * DK + c4;
        stcs2u(g_vals + off, make_uint2(pack2h(v.x, v.y), pack2h(v.z, v.w)));
    }
}

// ---------------- pre-kernels ----------------
__global__ void __launch_bounds__(256)
split_kernel(const float* __restrict__ src, __half* __restrict__ dh,
             __half* __restrict__ dl, size_t n)
{
    size_t i = ((size_t)blockIdx.x * 256 + threadIdx.x) * 4;
    if (i >= n) return;
    float4 v = *reinterpret_cast<const float4*>(src + i);
    uint32_t h0, l0, h1, l1;
    pack_split2h(v.x, v.y, h0, l0);
    pack_split2h(v.z, v.w, h1, l1);
    *reinterpret_cast<uint2*>(dh + i) = make_uint2(h0, h1);
    *reinterpret_cast<uint2*>(dl + i) = make_uint2(l0, l1);
}

__global__ void __launch_bounds__(256)
transpose_h(const float* __restrict__ W, __half* __restrict__ Th, int R, int C)
{
    __shared__ float t[32][33];
    int c0 = blockIdx.x * 32, r0 = blockIdx.y * 32;
    int tx = threadIdx.x & 31, ty = threadIdx.x >> 5;
    for (int j = ty; j < 32; j += 8)
        t[j][tx] = W[(size_t)(r0 + j) * C + c0 + tx];
    __syncthreads();
    for (int j = ty; j < 32; j += 8)
        Th[(size_t)(c0 + j) * R + r0 + tx] = __float2half(t[tx][j]);
}

// ---------------- launch ----------------
extern "C" void kernel_launch(void* const* d_in, const int* /*in_sizes*/, int /*n_in*/,
                              void* d_out, int /*out_size*/)
{
    const float* x    = (const float*)d_in[0];
    const float* Wqkv = (const float*)d_in[1];
    const float* bqkv = (const float*)d_in[2];
    const float* Wout = (const float*)d_in[3];
    const float* bout = (const float*)d_in[4];

    float* out  = (float*)d_out;
    float* attn = out + (size_t)M_TOK * E;

    __half *xhi, *xlo, *Wq, *Wo, *Qhi, *Qlo, *Kp, *Vt, *Vl;
    float *ri;
    cudaGetSymbolAddress((void**)&xhi, g_xhi);
    cudaGetSymbolAddress((void**)&xlo, g_xlo);
    cudaGetSymbolAddress((void**)&Wq,  g_Wqt);
    cudaGetSymbolAddress((void**)&Wo,  g_Wot);
    cudaGetSymbolAddress((void**)&Qhi, g_Qhi);
    cudaGetSymbolAddress((void**)&Qlo, g_Qlo);
    cudaGetSymbolAddress((void**)&Kp,  g_K);
    cudaGetSymbolAddress((void**)&Vt,  g_Vt);
    cudaGetSymbolAddress((void**)&Vl,  g_vals);
    cudaGetSymbolAddress((void**)&ri,  g_ri);

    constexpr int SM_QKV   = 92160;
    constexpr int SM_OUT   = 69632;
    constexpr int SM_STATS = 102400;
    constexpr int SM_PV2   = 111104;
    cudaFuncSetAttribute(gemm_async<128, 128, 2, EpiQKV>,
                         cudaFuncAttributeMaxDynamicSharedMemorySize, SM_QKV);
    cudaFuncSetAttribute(gemm_async<128, 128, 1, EpiOut>,
                         cudaFuncAttributeMaxDynamicSharedMemorySize, SM_OUT);
    cudaFuncSetAttribute(stats_kernel,
                         cudaFuncAttributeMaxDynamicSharedMemorySize, SM_STATS);
    cudaFuncSetAttribute(pv2_kernel,
                         cudaFuncAttributeMaxDynamicSharedMemorySize, SM_PV2);

    // 0) operand prep
    transpose_h<<<dim3(3 * E / 32, E / 32), 256>>>(Wqkv, Wq, E, 3 * E);
    transpose_h<<<dim3(E / 32, E / 32), 256>>>(Wout, Wo, E, E);
    split_kernel<<<(unsigned)((size_t)M_TOK * E / 4 / 256), 256>>>(x, xhi, xlo, (size_t)M_TOK * E);

    // 1) QKV projection (A = x split, 2-pass, 3-stage pipeline)
    gemm_async<128, 128, 2, EpiQKV><<<dim3(3 * E / 128, M_TOK / 128, 1), 256, SM_QKV>>>(
        xhi, xlo, Wq, E, 0, 0, EpiQKV{bqkv});

    // 2) stats: per-row 1/sum(exp(l/8)), warp-local reduce, 3-stage K pipeline
    stats_kernel<<<dim3(1, S / 128, BH), 256, SM_STATS>>>(Qhi, Qlo, Kp, ri);

    // 3) PV2: recompute logits, probs -> attn (streaming store), PV
    pv2_kernel<<<dim3(1, S / 128, BH), 256, SM_PV2>>>(attn, ri, Qhi, Qlo, Kp, Vt);

    // 4) output projection (A = vals single fp16, 1-pass)
    gemm_async<128, 128, 1, EpiOut><<<dim3(E / 128, M_TOK / 128, 1), 256, SM_OUT>>>(
        Vl, nullptr, Wo, E, 0, 0, EpiOut{bout, out});
}

// round 17
// speedup vs baseline: 1.5400x; 1.0094x over previous
#include <cuda_runtime.h>
#include <cuda_fp16.h>
#include <mma.h>
#include <cstdint>
#include <cstddef>
#include <math_constants.h>

using namespace nvcuda;

// Problem constants
static constexpr int B  = 4;
static constexpr int S  = 2048;
static constexpr int E  = 1024;
static constexpr int H  = 16;
static constexpr int DK = 64;
static constexpr int BH = B * H;      // 64
static constexpr int M_TOK = B * S;   // 8192

// ---------------- scratch (device globals; no cudaMalloc allowed) ----------------
__device__ __half g_xhi[(size_t)M_TOK * E], g_xlo[(size_t)M_TOK * E];
__device__ __half g_Wqt[(size_t)3 * E * E];
__device__ __half g_Wot[(size_t)E * E];
__device__ __half g_Qhi[(size_t)BH * S * DK], g_Qlo[(size_t)BH * S * DK];
__device__ __half g_K  [(size_t)BH * S * DK];
__device__ __half g_Vt [(size_t)BH * DK * S];
__device__ __half g_vals[(size_t)M_TOK * E];

// ---------------- helpers ----------------
__device__ __forceinline__ uint32_t smem_to_u32(const void* p) {
    uint32_t a;
    asm("{ .reg .u64 t; cvta.to.shared.u64 t, %1; cvt.u32.u64 %0, t; }" : "=r"(a) : "l"(p));
    return a;
}
__device__ __forceinline__ void cp_async16(uint32_t dst, const void* src) {
    asm volatile("cp.async.cg.shared.global [%0], [%1], 16;" :: "r"(dst), "l"(src));
}
#define CP_COMMIT() asm volatile("cp.async.commit_group;" ::: "memory")
#define CP_WAIT(N)  asm volatile("cp.async.wait_group %0;" :: "n"(N) : "memory")

__device__ __forceinline__ void stcs4(float* p, float4 v) {
    asm volatile("st.global.cs.v4.f32 [%0], {%1,%2,%3,%4};"
                 :: "l"(p), "f"(v.x), "f"(v.y), "f"(v.z), "f"(v.w) : "memory");
}
__device__ __forceinline__ void stcs2u(void* p, uint2 v) {
    asm volatile("st.global.cs.v2.u32 [%0], {%1,%2};"
                 :: "l"(p), "r"(v.x), "r"(v.y) : "memory");
}

__device__ __forceinline__ uint32_t pack2h(float a, float b) {
    __half2 p(__float2half(a), __float2half(b));
    return *reinterpret_cast<uint32_t*>(&p);
}
__device__ __forceinline__ void split2h(float v, __half& h, __half& l) {
    h = __float2half(v);
    l = __float2half(v - __half2float(h));
}
__device__ __forceinline__ void pack_split2h(float a, float b, uint32_t& hi, uint32_t& lo) {
    __half ha, la, hb, lb;
    split2h(a, ha, la); split2h(b, hb, lb);
    __half2 Hp(ha, hb), Lp(la, lb);
    hi = *reinterpret_cast<uint32_t*>(&Hp);
    lo = *reinterpret_cast<uint32_t*>(&Lp);
}

// ---------------- epilogues for projection GEMMs (BN=128, LDC=136) ----------------
struct EpiQKV {
    const float* bias;
    __device__ void run(int /*z*/, int m0, int n0, int tid, const float* Cs) const {
        #pragma unroll
        for (int it = 0; it < 16; it++) {
            int idx = it * 256 + tid;
            int r = idx >> 5;
            int c4 = (idx & 31) * 4;
            int c = n0 + c4;
            int h = c / 192, cc = c - h * 192;
            int t = cc >> 6, d0 = cc & 63;
            if (t == 2) continue;   // V handled by transposed path below
            float4 v = *reinterpret_cast<const float4*>(Cs + r * 136 + c4);
            v.x += bias[c]; v.y += bias[c + 1]; v.z += bias[c + 2]; v.w += bias[c + 3];
            int gr = m0 + r;
            int b = gr >> 11, s = gr & 2047;
            int bh = b * H + h;
            if (t == 1) {
                size_t off = ((size_t)bh * S + s) * DK + d0;
                *reinterpret_cast<uint2*>(g_K + off) =
                    make_uint2(pack2h(v.x, v.y), pack2h(v.z, v.w));
            } else {
                uint32_t h0, l0, h1, l1;
                pack_split2h(v.x, v.y, h0, l0);
                pack_split2h(v.z, v.w, h1, l1);
                size_t off = ((size_t)bh * S + s) * DK + d0;
                *reinterpret_cast<uint2*>(g_Qhi + off) = make_uint2(h0, h1);
                *reinterpret_cast<uint2*>(g_Qlo + off) = make_uint2(l0, l1);
            }
        }
        // ---- V columns: transposed, coalesced along s ----
        const int wid = tid >> 5, lane = tid & 31;
        const int b = m0 >> 11, s0 = m0 & 2047;
        #pragma unroll
        for (int half = 0; half < 2; half++) {
            int cbase = n0 + half * 64;
            int h = cbase / 192, cc = cbase - h * 192;
            if ((cc >> 6) != 2) continue;
            int bh = b * H + h;
            #pragma unroll
            for (int dd = 0; dd < 8; dd++) {
                int d = wid * 8 + dd;
                float bval = bias[cbase + d];
                __half* dst = g_Vt + ((size_t)bh * DK + d) * S + s0;
                #pragma unroll
                for (int sb = 0; sb < 4; sb++) {
                    int r = sb * 32 + lane;
                    float v = Cs[r * 136 + half * 64 + d] + bval;
                    dst[r] = __float2half(v);
                }
            }
        }
    }
};

struct EpiOut {
    const float* bias;
    float* out;
    __device__ void run(int /*z*/, int m0, int n0, int tid, const float* Cs) const {
        #pragma unroll
        for (int it = 0; it < 16; it++) {
            int idx = it * 256 + tid;
            int r = idx >> 5;
            int c4 = (idx & 31) * 4;
            float4 v = *reinterpret_cast<const float4*>(Cs + r * 136 + c4);
            int c = n0 + c4;
            v.x += bias[c]; v.y += bias[c + 1]; v.z += bias[c + 2]; v.w += bias[c + 3];
            stcs4(out + (size_t)(m0 + r) * E + c, v);
        }
    }
};

// ---------------- cp.async 3-stage pipelined fp16 WMMA GEMM (BK=32, 2 CTAs/SM) ----
template<int BM, int BN, int AP, class Epi>
__global__ void __launch_bounds__(256, 2)
gemm_async(const __half* __restrict__ Ahi, const __half* __restrict__ Alo,
           const __half* __restrict__ Bs, int K, size_t sAz, size_t sBz, Epi epi)
{
    constexpr int LD = 40;
    constexpr int STG_BYTES = (AP * BM + BN) * LD * 2;
    constexpr int WM = 32, WN = BN / 2;
    constexpr int MI = WM / 16, NI = WN / 16;
    constexpr int LDC = BN + 8;

    extern __shared__ char smem[];
    const uint32_t sbase = smem_to_u32(smem);
    const int tid = threadIdx.x, wid = tid >> 5;
    const int z = blockIdx.z;
    const int m0 = blockIdx.y * BM, n0 = blockIdx.x * BN;
    const int wm0 = (wid & 3) * WM, wn0 = (wid >> 2) * WN;

    Ahi += (size_t)z * sAz;
    if (AP == 2) Alo += (size_t)z * sAz;
    Bs += (size_t)z * sBz;

    const int nchunks = K >> 5;

    auto stage = [&](int s, int ch) {
        const int k0 = ch << 5;
        const uint32_t sA = sbase + s * STG_BYTES;
        const uint32_t sB = sA + AP * BM * LD * 2;
        for (int u = tid; u < BM * 4; u += 256) {
            int r = u >> 2, g = u & 3;
            size_t gi = (size_t)(m0 + r) * K + k0 + g * 8;
            uint32_t so = sA + (uint32_t)(r * LD + g * 8) * 2;
            cp_async16(so, Ahi + gi);
            if (AP == 2) cp_async16(so + BM * LD * 2, Alo + gi);
        }
        for (int u = tid; u < BN * 4; u += 256) {
            int r = u >> 2, g = u & 3;
            size_t gi = (size_t)(n0 + r) * K + k0 + g * 8;
            cp_async16(sB + (uint32_t)(r * LD + g * 8) * 2, Bs + gi);
        }
        CP_COMMIT();
    };

    wmma::fragment<wmma::accumulator, 16, 16, 16, float> acc[MI][NI];
    #pragma unroll
    for (int mi = 0; mi < MI; mi++)
        #pragma unroll
        for (int ni = 0; ni < NI; ni++) wmma::fill_fragment(acc[mi][ni], 0.0f);

    stage(0, 0);
    if (nchunks > 1) stage(1, 1);
    for (int ch = 0; ch < nchunks; ch++) {
        if (ch + 2 < nchunks) { stage((ch + 2) % 3, ch + 2); CP_WAIT(2); }
        else if (ch + 1 < nchunks) { CP_WAIT(1); }
        else { CP_WAIT(0); }
        __syncthreads();

        const __half* As_hi =
            reinterpret_cast<const __half*>(smem + (ch % 3) * STG_BYTES);
        const __half* As_lo = As_hi + BM * LD;
        const __half* Bs_s  = As_hi + AP * BM * LD;

        #pragma unroll
        for (int ks = 0; ks < 2; ks++) {
            wmma::fragment<wmma::matrix_a, 16, 16, 16, __half, wmma::row_major> ah[MI], al[MI];
            wmma::fragment<wmma::matrix_b, 16, 16, 16, __half, wmma::col_major> bf[NI];
            #pragma unroll
            for (int mi = 0; mi < MI; mi++) {
                wmma::load_matrix_sync(ah[mi], As_hi + (wm0 + mi * 16) * LD + ks * 16, LD);
                if (AP == 2)
                    wmma::load_matrix_sync(al[mi], As_lo + (wm0 + mi * 16) * LD + ks * 16, LD);
            }
            #pragma unroll
            for (int ni = 0; ni < NI; ni++)
                wmma::load_matrix_sync(bf[ni], Bs_s + (wn0 + ni * 16) * LD + ks * 16, LD);
            #pragma unroll
            for (int mi = 0; mi < MI; mi++)
                #pragma unroll
                for (int ni = 0; ni < NI; ni++) {
                    wmma::mma_sync(acc[mi][ni], ah[mi], bf[ni], acc[mi][ni]);
                    if (AP == 2)
                        wmma::mma_sync(acc[mi][ni], al[mi], bf[ni], acc[mi][ni]);
                }
        }
        __syncthreads();
    }

    float* Cs = reinterpret_cast<float*>(smem);
    #pragma unroll
    for (int mi = 0; mi < MI; mi++)
        #pragma unroll
        for (int ni = 0; ni < NI; ni++)
            wmma::store_matrix_sync(Cs + (wm0 + mi * 16) * LDC + wn0 + ni * 16,
                                    acc[mi][ni], LDC, wmma::mem_row_major);
    __syncthreads();
    epi.run(z, m0, n0, tid, Cs);
}

// ---------------- FUSED attention: stats (phase A) + recompute/probs/PV (phase B) --
// CTA = (z, 128-row strip). Q staged once; ri kept in smem (no gmem round trip).
// smem layout (bytes):
//   OFF_Q  = 0       Qh 18432 + Ql 18432                      (both phases)
//   OFF_K  = 36864   A: 3 x 9216 K stages  |  B: 2 x 9216 K
//   OFF_V  = 55296                            B: 2 x 9216 V   (A: unused)
//   OFF_C  = 73728   36864 fp32 accum scratch / fp16 probs overlay (LDP=144)
//   OFF_S2 = 110592  128*2*4 per-warp-half partial sums (phase A)
//   OFF_RI = 111616  128*4 row 1/sum ; total 112128  (2 CTAs/SM)
__global__ void __launch_bounds__(256, 2)
attn_fused(float* __restrict__ attn,
           const __half* __restrict__ Qhi, const __half* __restrict__ Qlo,
           const __half* __restrict__ Kp, const __half* __restrict__ Vt)
{
    constexpr int LDQ = 72, LDK = 72, LDV = 72, LDCF = 72, LDP = 144;
    constexpr int OFF_Q  = 0;
    constexpr int OFF_K  = 36864;
    constexpr int OFF_V  = 55296;
    constexpr int OFF_C  = 73728;
    constexpr int OFF_S2 = 110592;
    constexpr int OFF_RI = 111616;

    extern __shared__ char smem[];
    const uint32_t sbase = smem_to_u32(smem);
    const int tid = threadIdx.x, wid = tid >> 5, lane = tid & 31;
    const int z = blockIdx.z, m0 = blockIdx.y * 128;
    const int wm0 = (wid & 3) * 32, wn0 = (wid >> 2) * 32;
    const int whalf = wid >> 2;

    const __half* Qh_g = Qhi + ((size_t)z * S + m0) * DK;
    const __half* Ql_g = Qlo + ((size_t)z * S + m0) * DK;
    const __half* K_g  = Kp  + (size_t)z * S * DK;
    const __half* V_g  = Vt  + (size_t)z * DK * S;
    float* attnZ = attn + (size_t)z * S * S;

    // ---- Q staged once for both phases ----
    for (int u = tid; u < 128 * 8; u += 256) {
        int r = u >> 3, g = u & 7;
        cp_async16(sbase + OFF_Q + (uint32_t)(r * LDQ + g * 8) * 2, Qh_g + (size_t)r * DK + g * 8);
        cp_async16(sbase + OFF_Q + 18432 + (uint32_t)(r * LDQ + g * 8) * 2, Ql_g + (size_t)r * DK + g * 8);
    }
    CP_COMMIT();

    auto stage_k = [&](int s, int ch) {    // phase A: K only, 3 buffers
        int k0 = ch << 6;
        for (int u = tid; u < 64 * 8; u += 256) {
            int r = u >> 3, g = u & 7;
            cp_async16(sbase + OFF_K + s * 9216 + (uint32_t)(r * LDK + g * 8) * 2,
                       K_g + (size_t)(k0 + r) * DK + g * 8);
        }
        CP_COMMIT();
    };
    auto stage_kv = [&](int s, int ch) {   // phase B: K + V, 2 buffers
        int k0 = ch << 6;
        for (int u = tid; u < 64 * 8; u += 256) {
            int r = u >> 3, g = u & 7;
            cp_async16(sbase + OFF_K + s * 9216 + (uint32_t)(r * LDK + g * 8) * 2,
                       K_g + (size_t)(k0 + r) * DK + g * 8);
            cp_async16(sbase + OFF_V + s * 9216 + (uint32_t)(r * LDV + g * 8) * 2,
                       V_g + (size_t)r * S + k0 + g * 8);
        }
        CP_COMMIT();
    };

    stage_k(0, 0);
    stage_k(1, 1);

    float* sS2 = reinterpret_cast<float*>(smem + OFF_S2);
    float* sRi = reinterpret_cast<float*>(smem + OFF_RI);
    if (tid < 256) sS2[tid] = 0.0f;

    const __half* sQh = reinterpret_cast<const __half*>(smem + OFF_Q);
    const __half* sQl = reinterpret_cast<const __half*>(smem + OFF_Q + 18432);
    float* Csf = reinterpret_cast<float*>(smem + OFF_C);
    __half* PhB = reinterpret_cast<__half*>(smem + OFF_C);

    // ================= PHASE A: row sums of exp(l/8) =================
    for (int ch = 0; ch < 32; ch++) {
        __syncthreads();   // prev MMA done: stage buffer (ch+2)%3 reusable
        if (ch + 2 < 32) { stage_k((ch + 2) % 3, ch + 2); CP_WAIT(2); }
        else if (ch + 1 < 32) { CP_WAIT(1); }
        else { CP_WAIT(0); }
        __syncthreads();   // K[ch] visible
        const __half* sK = reinterpret_cast<const __half*>(smem + OFF_K + (ch % 3) * 9216);

        wmma::fragment<wmma::accumulator, 16, 16, 16, float> acc[2][2];
        #pragma unroll
        for (int mi = 0; mi < 2; mi++)
            #pragma unroll
            for (int ni = 0; ni < 2; ni++) wmma::fill_fragment(acc[mi][ni], 0.0f);

        #pragma unroll
        for (int ks = 0; ks < 4; ks++) {
            wmma::fragment<wmma::matrix_a, 16, 16, 16, __half, wmma::row_major> ah[2], al[2];
            wmma::fragment<wmma::matrix_b, 16, 16, 16, __half, wmma::col_major> bf[2];
            #pragma unroll
            for (int mi = 0; mi < 2; mi++) {
                wmma::load_matrix_sync(ah[mi], sQh + (wm0 + mi * 16) * LDQ + ks * 16, LDQ);
                wmma::load_matrix_sync(al[mi], sQl + (wm0 + mi * 16) * LDQ + ks * 16, LDQ);
            }
            #pragma unroll
            for (int ni = 0; ni < 2; ni++)
                wmma::load_matrix_sync(bf[ni], sK + (wn0 + ni * 16) * LDK + ks * 16, LDK);
            #pragma unroll
            for (int mi = 0; mi < 2; mi++)
                #pragma unroll
                for (int ni = 0; ni < 2; ni++) {
                    wmma::mma_sync(acc[mi][ni], ah[mi], bf[ni], acc[mi][ni]);
                    wmma::mma_sync(acc[mi][ni], al[mi], bf[ni], acc[mi][ni]);
                }
        }
        // warp-local reduce of own 32x32 tile
        #pragma unroll
        for (int mi = 0; mi < 2; mi++)
            #pragma unroll
            for (int ni = 0; ni < 2; ni++)
                wmma::store_matrix_sync(Csf + (wm0 + mi * 16) * LDCF + wn0 + ni * 16,
                                        acc[mi][ni], LDCF, wmma::mem_row_major);
        __syncwarp();
        #pragma unroll
        for (int j = 0; j < 8; j++) {
            int r = wm0 + j * 4 + (lane >> 3);
            int c4 = wn0 + (lane & 7) * 4;
            float4 v = *reinterpret_cast<const float4*>(Csf + r * LDCF + c4);
            float ts = __expf(v.x * 0.125f) + __expf(v.y * 0.125f)
                     + __expf(v.z * 0.125f) + __expf(v.w * 0.125f);
            #pragma unroll
            for (int o = 4; o > 0; o >>= 1) ts += __shfl_xor_sync(0xFFFFFFFFu, ts, o);
            if ((lane & 7) == 0) sS2[r * 2 + whalf] += ts;
        }
        __syncwarp();
    }
    __syncthreads();

    // ---- transition: ri = 1/Σ, in smem only ----
    if (tid < 128) sRi[tid] = 1.0f / (sS2[tid * 2] + sS2[tid * 2 + 1]);
    stage_kv(0, 0);

    // ================= PHASE B: recompute, probs -> attn, PV =================
    wmma::fragment<wmma::accumulator, 16, 16, 16, float> pacc[2][2];
    #pragma unroll
    for (int mi = 0; mi < 2; mi++)
        #pragma unroll
        for (int ni = 0; ni < 2; ni++) wmma::fill_fragment(pacc[mi][ni], 0.0f);

    for (int ch = 0; ch < 32; ch++) {
        __syncthreads();   // prev PV MMA done (and at ch=0: sRi visible, buffers free)

        if (ch + 1 < 32) { stage_kv((ch + 1) & 1, ch + 1); CP_WAIT(1); }
        else             { CP_WAIT(0); }
        __syncthreads();   // KV[ch] visible

        const __half* sK = reinterpret_cast<const __half*>(smem + OFF_K + (ch & 1) * 9216);
        const __half* sV = reinterpret_cast<const __half*>(smem + OFF_V + (ch & 1) * 9216);

        // ---- QK^T recompute (identical arithmetic to phase A) ----
        wmma::fragment<wmma::accumulator, 16, 16, 16, float> qacc[2][2];
        #pragma unroll
        for (int mi = 0; mi < 2; mi++)
            #pragma unroll
            for (int ni = 0; ni < 2; ni++) wmma::fill_fragment(qacc[mi][ni], 0.0f);
        #pragma unroll
        for (int ks = 0; ks < 4; ks++) {
            wmma::fragment<wmma::matrix_a, 16, 16, 16, __half, wmma::row_major> ah[2], al[2];
            wmma::fragment<wmma::matrix_b, 16, 16, 16, __half, wmma::col_major> bf[2];
            #pragma unroll
            for (int mi = 0; mi < 2; mi++) {
                wmma::load_matrix_sync(ah[mi], sQh + (wm0 + mi * 16) * LDQ + ks * 16, LDQ);
                wmma::load_matrix_sync(al[mi], sQl + (wm0 + mi * 16) * LDQ + ks * 16, LDQ);
            }
            #pragma unroll
            for (int ni = 0; ni < 2; ni++)
                wmma::load_matrix_sync(bf[ni], sK + (wn0 + ni * 16) * LDK + ks * 16, LDK);
            #pragma unroll
            for (int mi = 0; mi < 2; mi++)
                #pragma unroll
                for (int ni = 0; ni < 2; ni++) {
                    wmma::mma_sync(qacc[mi][ni], ah[mi], bf[ni], qacc[mi][ni]);
                    wmma::mma_sync(qacc[mi][ni], al[mi], bf[ni], qacc[mi][ni]);
                }
        }
        #pragma unroll
        for (int mi = 0; mi < 2; mi++)
            #pragma unroll
            for (int ni = 0; ni < 2; ni++)
                wmma::store_matrix_sync(Csf + (wm0 + mi * 16) * LDCF + wn0 + ni * 16,
                                        qacc[mi][ni], LDCF, wmma::mem_row_major);
        __syncthreads();

        // ---- transform: exp/Σ, probs -> attn (streaming), warp-local fp16 pack ----
        const int n0 = ch << 6;
        #pragma unroll
        for (int it = 0; it < 8; it++) {
            int idx = it * 256 + tid;
            int r = idx >> 4, c4 = (idx & 15) * 4;   // row handled within one warp
            float4 v = *reinterpret_cast<const float4*>(Csf + r * LDCF + c4);
            float rv = sRi[r];
            float4 p;
            p.x = __expf(v.x * 0.125f) * rv;
            p.y = __expf(v.y * 0.125f) * rv;
            p.z = __expf(v.z * 0.125f) * rv;
            p.w = __expf(v.w * 0.125f) * rv;
            stcs4(attnZ + (size_t)(m0 + r) * S + n0 + c4, p);
            __syncwarp();
            *reinterpret_cast<uint2*>(PhB + r * LDP + c4) =
                make_uint2(pack2h(p.x, p.y), pack2h(p.z, p.w));
        }
        __syncthreads();

        // ---- PV MMA, single pass on fp16 probs ----
        #pragma unroll
        for (int ks = 0; ks < 4; ks++) {
            wmma::fragment<wmma::matrix_a, 16, 16, 16, __half, wmma::row_major> af[2];
            wmma::fragment<wmma::matrix_b, 16, 16, 16, __half, wmma::col_major> bf[2];
            #pragma unroll
            for (int mi = 0; mi < 2; mi++)
                wmma::load_matrix_sync(af[mi], PhB + (wm0 + mi * 16) * LDP + ks * 16, LDP);
            #pragma unroll
            for (int ni = 0; ni < 2; ni++)
                wmma::load_matrix_sync(bf[ni], sV + (wn0 + ni * 16) * LDV + ks * 16, LDV);
            #pragma unroll
            for (int mi = 0; mi < 2; mi++)
                #pragma unroll
                for (int ni = 0; ni < 2; ni++)
                    wmma::mma_sync(pacc[mi][ni], af[mi], bf[ni], pacc[mi][ni]);
        }
    }
    __syncthreads();

    // ---- epilogue: values -> g_vals single fp16 [B,S,E] ----
    #pragma unroll
    for (int mi = 0; mi < 2; mi++)
        #pragma unroll
        for (int ni = 0; ni < 2; ni++)
            wmma::store_matrix_sync(Csf + (wm0 + mi * 16) * 72 + wn0 + ni * 16,
                                    pacc[mi][ni], 72, wmma::mem_row_major);
    __syncthreads();

    int b = z >> 4, h = z & 15;
    #pragma unroll
    for (int it = 0; it < 8; it++) {
        int idx = it * 256 + tid;
        int r = idx >> 4;
        int c4 = (idx & 15) * 4;
        float4 v = *reinterpret_cast<const float4*>(Csf + r * 72 + c4);
        size_t off = (size_t)(b * S + m0 + r) * E + h * DK + c4;
        stcs2u(g_vals + off, make_uint2(pack2h(v.x, v.y), pack2h(v.z, v.w)));
    }
}

// ---------------- pre-kernels ----------------
__global__ void __launch_bounds__(256)
split_kernel(const float* __restrict__ src, __half* __restrict__ dh,
             __half* __restrict__ dl, size_t n)
{
    size_t i = ((size_t)blockIdx.x * 256 + threadIdx.x) * 4;
    if (i >= n) return;
    float4 v = *reinterpret_cast<const float4*>(src + i);
    uint32_t h0, l0, h1, l1;
    pack_split2h(v.x, v.y, h0, l0);
    pack_split2h(v.z, v.w, h1, l1);
    *reinterpret_cast<uint2*>(dh + i) = make_uint2(h0, h1);
    *reinterpret_cast<uint2*>(dl + i) = make_uint2(l0, l1);
}

__global__ void __launch_bounds__(256)
transpose_h(const float* __restrict__ W, __half* __restrict__ Th, int R, int C)
{
    __shared__ float t[32][33];
    int c0 = blockIdx.x * 32, r0 = blockIdx.y * 32;
    int tx = threadIdx.x & 31, ty = threadIdx.x >> 5;
    for (int j = ty; j < 32; j += 8)
        t[j][tx] = W[(size_t)(r0 + j) * C + c0 + tx];
    __syncthreads();
    for (int j = ty; j < 32; j += 8)
        Th[(size_t)(c0 + j) * R + r0 + tx] = __float2half(t[tx][j]);
}

// ---------------- launch ----------------
extern "C" void kernel_launch(void* const* d_in, const int* /*in_sizes*/, int /*n_in*/,
                              void* d_out, int /*out_size*/)
{
    const float* x    = (const float*)d_in[0];
    const float* Wqkv = (const float*)d_in[1];
    const float* bqkv = (const float*)d_in[2];
    const float* Wout = (const float*)d_in[3];
    const float* bout = (const float*)d_in[4];

    float* out  = (float*)d_out;
    float* attn = out + (size_t)M_TOK * E;

    __half *xhi, *xlo, *Wq, *Wo, *Qhi, *Qlo, *Kp, *Vt, *Vl;
    cudaGetSymbolAddress((void**)&xhi, g_xhi);
    cudaGetSymbolAddress((void**)&xlo, g_xlo);
    cudaGetSymbolAddress((void**)&Wq,  g_Wqt);
    cudaGetSymbolAddress((void**)&Wo,  g_Wot);
    cudaGetSymbolAddress((void**)&Qhi, g_Qhi);
    cudaGetSymbolAddress((void**)&Qlo, g_Qlo);
    cudaGetSymbolAddress((void**)&Kp,  g_K);
    cudaGetSymbolAddress((void**)&Vt,  g_Vt);
    cudaGetSymbolAddress((void**)&Vl,  g_vals);

    constexpr int SM_QKV  = 92160;
    constexpr int SM_OUT  = 69632;
    constexpr int SM_ATTN = 112128;
    cudaFuncSetAttribute(gemm_async<128, 128, 2, EpiQKV>,
                         cudaFuncAttributeMaxDynamicSharedMemorySize, SM_QKV);
    cudaFuncSetAttribute(gemm_async<128, 128, 1, EpiOut>,
                         cudaFuncAttributeMaxDynamicSharedMemorySize, SM_OUT);
    cudaFuncSetAttribute(attn_fused,
                         cudaFuncAttributeMaxDynamicSharedMemorySize, SM_ATTN);

    // 0) operand prep
    transpose_h<<<dim3(3 * E / 32, E / 32), 256>>>(Wqkv, Wq, E, 3 * E);
    transpose_h<<<dim3(E / 32, E / 32), 256>>>(Wout, Wo, E, E);
    split_kernel<<<(unsigned)((size_t)M_TOK * E / 4 / 256), 256>>>(x, xhi, xlo, (size_t)M_TOK * E);

    // 1) QKV projection (A = x split, 2-pass, 3-stage pipeline)
    gemm_async<128, 128, 2, EpiQKV><<<dim3(3 * E / 128, M_TOK / 128, 1), 256, SM_QKV>>>(
        xhi, xlo, Wq, E, 0, 0, EpiQKV{bqkv});

    // 2) fused attention: stats + recompute + probs + PV in one kernel
    attn_fused<<<dim3(1, S / 128, BH), 256, SM_ATTN>>>(attn, Qhi, Qlo, Kp, Vt);

    // 3) output projection (A = vals single fp16, 1-pass)
    gemm_async<128, 128, 1, EpiOut><<<dim3(E / 128, M_TOK / 128, 1), 256, SM_OUT>>>(
        Vl, nullptr, Wo, E, 0, 0, EpiOut{bout, out});
}